// round 13
// baseline (speedup 1.0000x reference)
#include <cuda_runtime.h>
#include <cuda_fp16.h>
#include <cstdint>
#include <math.h>

// ---------------- fixed problem shapes ----------------
#define N_TOK   32760          // 21 * 1560
#define DIM     1536
#define NHEADS  12
#define HD      128
#define S_SP    1560
#define N_T     21
#define ENC     768
#define NA      32
#define KV_ROWS 672
#define PKDIM   384            // NHEADS * NA
#define LOG2_10000 13.287712379549449f

// ---------------- scratch ----------------
__device__ __half g_xh[N_TOK * DIM];          // fp16 x
__device__ __half g_qh[N_TOK * DIM];          // fp16 RoPE'd q
__device__ __half g_qwh[DIM * DIM];           // fp16 q_w
__device__ __half g_pwh[DIM * DIM];           // fp16 proj_w
__device__ __half g_ehsh[KV_ROWS * ENC];      // fp16 encoder states
__device__ __half g_kvwh[2 * DIM * ENC];      // fp16 kv_w
__device__ float  g_k[KV_ROWS * DIM];         // RoPE'd k (fp32)
__device__ __half g_vh[KV_ROWS * DIM];        // v (fp16)
__device__ __half g_probsh[N_TOK * PKDIM];    // softmax probs [t*S+s][h*32+a]
__device__ __half g_w2h[N_T * DIM * PKDIM];   // W2^T [b][c][h*32+a]
__device__ float  g_pos[N_TOK];
__device__ float  g_mm[4];

// ---------------- helpers ----------------
__device__ __forceinline__ uint32_t smem_u32(const void* p) {
    uint32_t r;
    asm("{.reg .u64 t; cvta.to.shared.u64 t, %1; cvt.u32.u64 %0, t;}" : "=r"(r) : "l"(p));
    return r;
}

#define LDSM4(r0, r1, r2, r3, addr)                                            \
    asm volatile("ldmatrix.sync.aligned.m8n8.x4.shared.b16 {%0,%1,%2,%3}, [%4];" \
                 : "=r"(r0), "=r"(r1), "=r"(r2), "=r"(r3) : "r"(addr))

#define MMA_F16(d, a, b0, b1)                                                  \
    asm volatile("mma.sync.aligned.m16n8k16.row.col.f32.f16.f16.f32 "           \
                 "{%0,%1,%2,%3},{%4,%5,%6,%7},{%8,%9},{%0,%1,%2,%3};"          \
                 : "+f"(d[0]), "+f"(d[1]), "+f"(d[2]), "+f"(d[3])              \
                 : "r"(a[0]), "r"(a[1]), "r"(a[2]), "r"(a[3]), "r"(b0), "r"(b1))

// ---------------- fp32 -> fp16 conversion (4x ILP) ----------------
__global__ void cvt_half_kernel(const float* __restrict__ in, __half* __restrict__ out, int n4) {
    int base = blockIdx.x * (blockDim.x * 4) + threadIdx.x;
    float4 v[4];
    bool ok[4];
#pragma unroll
    for (int g = 0; g < 4; g++) {
        int i = base + g * blockDim.x;
        ok[g] = (i < n4);
        if (ok[g]) v[g] = ((const float4*)in)[i];
    }
#pragma unroll
    for (int g = 0; g < 4; g++) {
        if (ok[g]) {
            int i = base + g * blockDim.x;
            __half2 h0 = __floats2half2_rn(v[g].x, v[g].y);
            __half2 h1 = __floats2half2_rn(v[g].z, v[g].w);
            uint2 pk;
            pk.x = *(uint32_t*)&h0;
            pk.y = *(uint32_t*)&h1;
            ((uint2*)out)[i] = pk;
        }
    }
}
#define CVT_GRID(n4) (((n4) + 1023) / 1024)

// ---------------- min/max of attn-map rows (single CTA, float4) ----------------
__global__ void minmax_kernel(const float* __restrict__ m) {
    __shared__ float s0[512], s1[512], s2[512], s3[512];
    int tid = threadIdx.x;
    float mn0 = 1e30f, mx0 = -1e30f, mn1 = 1e30f, mx1 = -1e30f;
    const float4* m0v = (const float4*)m;
    const float4* m1v = (const float4*)(m + N_TOK);
    for (int i = tid; i < N_TOK / 4; i += 512) {
        float4 v0 = m0v[i], v1 = m1v[i];
        mn0 = fminf(mn0, fminf(fminf(v0.x, v0.y), fminf(v0.z, v0.w)));
        mx0 = fmaxf(mx0, fmaxf(fmaxf(v0.x, v0.y), fmaxf(v0.z, v0.w)));
        mn1 = fminf(mn1, fminf(fminf(v1.x, v1.y), fminf(v1.z, v1.w)));
        mx1 = fmaxf(mx1, fmaxf(fmaxf(v1.x, v1.y), fmaxf(v1.z, v1.w)));
    }
    s0[tid] = mn0; s1[tid] = mx0; s2[tid] = mn1; s3[tid] = mx1;
    __syncthreads();
    for (int off = 256; off > 0; off >>= 1) {
        if (tid < off) {
            s0[tid] = fminf(s0[tid], s0[tid + off]);
            s1[tid] = fmaxf(s1[tid], s1[tid + off]);
            s2[tid] = fminf(s2[tid], s2[tid + off]);
            s3[tid] = fmaxf(s3[tid], s3[tid + off]);
        }
        __syncthreads();
    }
    if (tid == 0) { g_mm[0] = s0[0]; g_mm[1] = s1[0]; g_mm[2] = s2[0]; g_mm[3] = s3[0]; }
}

// ---------------- routing positions ----------------
__global__ void pos_kernel(const float* __restrict__ m) {
    int n = blockIdx.x * blockDim.x + threadIdx.x;
    if (n >= N_TOK) return;
    float m0 = m[n], m1 = m[N_TOK + n];
    float r;
    if (m0 >= m1) r = (m0 - g_mm[0]) / (g_mm[1] - g_mm[0] + 1e-8f) * 4.0f;
    else          r = (m1 - g_mm[2]) / (g_mm[3] - g_mm[2] + 1e-8f) * 4.0f + 20.0f;
    g_pos[n] = r;
}

// ======== fp16 GEMM: CTA 128x128, 3-stage, occ 2, fragment double-buffer ========
#define KCHUNK  64
#define SSTAGES 3
#define SSM_SZ  16384
#define SSM_TOT (SSTAGES * 2 * SSM_SZ)          // 98304

__device__ __forceinline__ void fill_stage_s(
    const __half* __restrict__ A, const __half* __restrict__ B, int M, int K,
    int row0, int col0, int kt, uint32_t sA, uint32_t sB, int tid)
{
#pragma unroll
    for (int g = 0; g < 4; g++) {
        int ga = tid + g * 256;
        int row = ga >> 3, ch = ga & 7;
        uint32_t dst = sA + (uint32_t)row * 128u + (((uint32_t)ch * 16u) ^ (((uint32_t)row & 7u) << 4));
        const __half* src = A + (size_t)(row0 + row) * K + kt * KCHUNK + ch * 8;
        int sz = (row0 + row < M) ? 16 : 0;
        asm volatile("cp.async.cg.shared.global [%0], [%1], 16, %2;" :: "r"(dst), "l"(src), "r"(sz));
    }
#pragma unroll
    for (int g = 0; g < 4; g++) {
        int gb = tid + g * 256;
        int row = gb >> 3, ch = gb & 7;
        uint32_t dst = sB + (uint32_t)row * 128u + (((uint32_t)ch * 16u) ^ (((uint32_t)row & 7u) << 4));
        const __half* src = B + (size_t)(col0 + row) * K + kt * KCHUNK + ch * 8;
        asm volatile("cp.async.cg.shared.global [%0], [%1], 16;" :: "r"(dst), "l"(src));
    }
    asm volatile("cp.async.commit_group;");
}

// FUSE_ROPE: q epilogue (RoPE + fp16 out). KV_EPI: kv epilogue (RoPE k->fp32, v->fp16).
// otherwise: bias + (HALF_OUT ? fp16 : fp32) store.
template <bool FUSE_ROPE, bool HALF_OUT, bool KV_EPI>
__global__ void __launch_bounds__(256, 2) gemm_f16_small(
    const __half* __restrict__ A, const __half* __restrict__ B,
    const float* __restrict__ bias, void* __restrict__ Cv,
    int M, int N, int K, size_t strA, size_t strB, size_t strC)
{
    extern __shared__ float smem[];
    const int tid  = threadIdx.x;
    const int lane = tid & 31, warp = tid >> 5;
    const int wm = warp >> 2, wn = warp & 3;      // 2x4 warp grid, warp tile 64x32
    const int row0 = blockIdx.y * 128, col0 = blockIdx.x * 128;

    A += (size_t)blockIdx.z * strA;
    B += (size_t)blockIdx.z * strB;

    const uint32_t sA = smem_u32(smem);
    const uint32_t sB = sA + SSTAGES * SSM_SZ;
    const int ktiles = K / KCHUNK;

    fill_stage_s(A, B, M, K, row0, col0, 0, sA, sB, tid);
    fill_stage_s(A, B, M, K, row0, col0, 1, sA + SSM_SZ, sB + SSM_SZ, tid);

    float acc[4][4][4];
#pragma unroll
    for (int i = 0; i < 4; i++)
#pragma unroll
        for (int j = 0; j < 4; j++)
#pragma unroll
            for (int k = 0; k < 4; k++) acc[i][j][k] = 0.0f;

    const int aRow = wm * 64 + ((lane >> 3) & 1) * 8 + (lane & 7);
    const int bRow = wn * 32 + ((lane >> 3) & 1) * 8 + (lane & 7);
    const uint32_t colSel = ((lane >> 4) & 1) * 16;
    const uint32_t xorv = ((uint32_t)lane & 7u) << 4;

    uint32_t a[2][4][4], bb[2][2][4];   // double-buffered fragments

#define LOAD_FRAGS(buf, bA_, bB_, ksv)                                          \
    do {                                                                        \
        const uint32_t cb = ((uint32_t)((ksv) * 32) + colSel) ^ xorv;           \
        _Pragma("unroll")                                                       \
        for (int mf = 0; mf < 4; mf++) {                                        \
            uint32_t ad = (bA_) + (uint32_t)(aRow + mf * 16) * 128 + cb;        \
            LDSM4(a[buf][mf][0], a[buf][mf][1], a[buf][mf][2], a[buf][mf][3], ad); \
        }                                                                       \
        _Pragma("unroll")                                                       \
        for (int ng = 0; ng < 2; ng++) {                                        \
            uint32_t bd = (bB_) + (uint32_t)(bRow + ng * 16) * 128 + cb;        \
            LDSM4(bb[buf][ng][0], bb[buf][ng][1], bb[buf][ng][2], bb[buf][ng][3], bd); \
        }                                                                       \
    } while (0)

    for (int it = 0; it < ktiles; it++) {
        if (it < ktiles - 1) asm volatile("cp.async.wait_group 1;" ::: "memory");
        else                 asm volatile("cp.async.wait_group 0;" ::: "memory");
        __syncthreads();
        const int st = it % 3;
        const uint32_t bA = sA + st * SSM_SZ;
        const uint32_t bB = sB + st * SSM_SZ;

        LOAD_FRAGS(0, bA, bB, 0);
#pragma unroll
        for (int ks = 0; ks < 4; ks++) {
            const int cur = ks & 1;
            if (ks < 3) LOAD_FRAGS((cur ^ 1), bA, bB, ks + 1);
#pragma unroll
            for (int mf = 0; mf < 4; mf++)
#pragma unroll
                for (int nf = 0; nf < 4; nf++) {
                    const int ng = nf >> 1, lo = nf & 1;
                    MMA_F16(acc[mf][nf], a[cur][mf], bb[cur][ng][lo], bb[cur][ng][2 + lo]);
                }
        }
        if (it + 2 < ktiles) {
            const int r = it + 2;
            fill_stage_s(A, B, M, K, row0, col0, r,
                         sA + (r % 3) * SSM_SZ, sB + (r % 3) * SSM_SZ, tid);
        }
    }
#undef LOAD_FRAGS

    // epilogue: c0,c1 at (row=lane>>2, col=2*(lane&3)); c2,c3 at row+8
#pragma unroll
    for (int mf = 0; mf < 4; mf++) {
        const int r0 = row0 + wm * 64 + mf * 16 + (lane >> 2);
        const int r8 = r0 + 8;
        float pos0 = 0.f, pos8 = 0.f;
        if (FUSE_ROPE) {
            pos0 = g_pos[(r0 < M) ? r0 : 0];
            pos8 = g_pos[(r8 < M) ? r8 : 0];
        }
        if (KV_EPI) {
            pos0 = ((r0 & 31) < 16) ? 2.0f : 22.0f;
            pos8 = ((r8 & 31) < 16) ? 2.0f : 22.0f;
        }
#pragma unroll
        for (int nf = 0; nf < 4; nf++) {
            const int c = col0 + wn * 32 + nf * 8 + (lane & 3) * 2;
            const float2 bv = *(const float2*)(bias + c);
            float o0 = acc[mf][nf][0] + bv.x;
            float o1 = acc[mf][nf][1] + bv.y;
            float o2 = acc[mf][nf][2] + bv.x;
            float o3 = acc[mf][nf][3] + bv.y;
            if (FUSE_ROPE || (KV_EPI && c < DIM)) {
                const int i = (c & 127) >> 1;   // RoPE pair index within the 128-d head
                const float fr = exp2f(-(float)i * (LOG2_10000 / 64.0f));
                float sn, cs;
                sincosf(pos0 * fr, &sn, &cs);
                float t0 = o0 * cs - o1 * sn;
                o1 = o1 * cs + o0 * sn; o0 = t0;
                sincosf(pos8 * fr, &sn, &cs);
                float t2 = o2 * cs - o3 * sn;
                o3 = o3 * cs + o2 * sn; o2 = t2;
            }
            if (KV_EPI) {
                if (c < DIM) {   // k half: fp32
                    if (r0 < M) *(float2*)(g_k + (size_t)r0 * DIM + c) = make_float2(o0, o1);
                    if (r8 < M) *(float2*)(g_k + (size_t)r8 * DIM + c) = make_float2(o2, o3);
                } else {         // v half: fp16
                    if (r0 < M) *(__half2*)(g_vh + (size_t)r0 * DIM + c - DIM) = __floats2half2_rn(o0, o1);
                    if (r8 < M) *(__half2*)(g_vh + (size_t)r8 * DIM + c - DIM) = __floats2half2_rn(o2, o3);
                }
            } else if (HALF_OUT) {
                __half* C = (__half*)Cv + (size_t)blockIdx.z * strC;
                if (r0 < M) *(__half2*)(C + (size_t)r0 * N + c) = __floats2half2_rn(o0, o1);
                if (r8 < M) *(__half2*)(C + (size_t)r8 * N + c) = __floats2half2_rn(o2, o3);
            } else {
                float* C = (float*)Cv + (size_t)blockIdx.z * strC;
                if (r0 < M) *(float2*)(C + (size_t)r0 * N + c) = make_float2(o0, o1);
                if (r8 < M) *(float2*)(C + (size_t)r8 * N + c) = make_float2(o2, o3);
            }
        }
    }
}

// ---------------- attention probs (float-staged q; s-split 4-way) ----------
#define S_CHUNK 390
__global__ void __launch_bounds__(256) attn_probs_kernel() {
    const int h = blockIdx.x;
    const int t = blockIdx.y;
    const int chunk = blockIdx.z;
    __shared__ float ks[32][132];
    __shared__ float qs[8][128];

    const int tid = threadIdx.x;
    for (int i = tid; i < 32 * 128; i += 256) {
        int a = i >> 7, d = i & 127;
        ks[a][d] = g_k[(size_t)(t * 32 + a) * DIM + h * HD + d];
    }
    __syncthreads();

    const int w = tid >> 5, l = tid & 31;
    const int sBeg = chunk * S_CHUNK;
    const int sEnd = (sBeg + S_CHUNK < S_SP) ? sBeg + S_CHUNK : S_SP;

    for (int s = sBeg + w; s < sEnd; s += 8) {
        size_t qoff = (size_t)(t * S_SP + s) * DIM + h * HD;
        uint2 qp = *(const uint2*)(g_qh + qoff + 4 * l);
        float2 f0 = __half22float2(*(__half2*)&qp.x);
        float2 f1 = __half22float2(*(__half2*)&qp.y);
        *(float4*)&qs[w][4 * l] = make_float4(f0.x, f0.y, f1.x, f1.y);
        __syncwarp();

        float acc = 0.0f;
        const float4* qr = (const float4*)&qs[w][0];
        const float4* kr = (const float4*)&ks[l][0];
#pragma unroll
        for (int j = 0; j < 32; j++) {
            float4 a4 = qr[j];
            float4 b4 = kr[j];
            acc += a4.x * b4.x + a4.y * b4.y + a4.z * b4.z + a4.w * b4.w;
        }
        acc *= 0.08838834764831845f;

        float mx = acc;
#pragma unroll
        for (int o = 16; o > 0; o >>= 1) mx = fmaxf(mx, __shfl_xor_sync(0xFFFFFFFFu, mx, o));
        float e = __expf(acc - mx);
        float sum = e;
#pragma unroll
        for (int o = 16; o > 0; o >>= 1) sum += __shfl_xor_sync(0xFFFFFFFFu, sum, o);
        float p = e / sum;

        g_probsh[(size_t)(t * S_SP + s) * PKDIM + h * NA + l] = __float2half_rn(p);
        __syncwarp();
    }
}

// ---------------- W2 fold on tensor cores ------------------------------------
__global__ void __launch_bounds__(128) w2_mma_kernel() {
    const int mt = blockIdx.x;
    const int h  = blockIdx.y;
    const int b  = blockIdx.z;
    __shared__ __align__(16) char smem[2 * 16384 + 2 * 4096];

    const int tid = threadIdx.x;
    const int lane = tid & 31, warp = tid >> 5;
    const uint32_t sA = smem_u32(smem);
    const uint32_t sB = sA + 2 * 16384;

#pragma unroll
    for (int g = 0; g < 16; g++) {
        int i = tid + g * 128;
        int kt = i >> 10, row = (i >> 3) & 127, ch = i & 7;
        uint32_t dst = sA + kt * 16384 + (uint32_t)row * 128u +
                       (((uint32_t)ch * 16u) ^ (((uint32_t)row & 7u) << 4));
        const __half* src = g_pwh + (size_t)(mt * 128 + row) * DIM + h * HD + kt * KCHUNK + ch * 8;
        asm volatile("cp.async.cg.shared.global [%0], [%1], 16;" :: "r"(dst), "l"(src));
    }
#pragma unroll
    for (int g = 0; g < 4; g++) {
        int i = tid + g * 128;
        int kt = i >> 8, row = (i >> 3) & 31, ch = i & 7;
        uint32_t dst = sB + kt * 4096 + (uint32_t)row * 128u +
                       (((uint32_t)ch * 16u) ^ (((uint32_t)row & 7u) << 4));
        const __half* src = g_vh + (size_t)(b * 32 + row) * DIM + h * HD + kt * KCHUNK + ch * 8;
        asm volatile("cp.async.cg.shared.global [%0], [%1], 16;" :: "r"(dst), "l"(src));
    }
    asm volatile("cp.async.commit_group;");
    asm volatile("cp.async.wait_group 0;" ::: "memory");
    __syncthreads();

    float acc[2][4][4];
#pragma unroll
    for (int i = 0; i < 2; i++)
#pragma unroll
        for (int j = 0; j < 4; j++)
#pragma unroll
            for (int k = 0; k < 4; k++) acc[i][j][k] = 0.0f;

    const int aRow = warp * 32 + ((lane >> 3) & 1) * 8 + (lane & 7);
    const int bRow = ((lane >> 3) & 1) * 8 + (lane & 7);
    const uint32_t colSel = ((lane >> 4) & 1) * 16;
    const uint32_t xorv = ((uint32_t)lane & 7u) << 4;

#pragma unroll
    for (int kt = 0; kt < 2; kt++) {
        const uint32_t bA = sA + kt * 16384;
        const uint32_t bB = sB + kt * 4096;
#pragma unroll
        for (int ks = 0; ks < 4; ks++) {
            uint32_t a[2][4], bb[2][4];
            const uint32_t cb = ((uint32_t)(ks * 32) + colSel) ^ xorv;
#pragma unroll
            for (int mf = 0; mf < 2; mf++) {
                uint32_t ad = bA + (uint32_t)(aRow + mf * 16) * 128 + cb;
                LDSM4(a[mf][0], a[mf][1], a[mf][2], a[mf][3], ad);
            }
#pragma unroll
            for (int ng = 0; ng < 2; ng++) {
                uint32_t bd = bB + (uint32_t)(bRow + ng * 16) * 128 + cb;
                LDSM4(bb[ng][0], bb[ng][1], bb[ng][2], bb[ng][3], bd);
            }
#pragma unroll
            for (int mf = 0; mf < 2; mf++)
#pragma unroll
                for (int nf = 0; nf < 4; nf++) {
                    const int ng = nf >> 1, lo = nf & 1;
                    MMA_F16(acc[mf][nf], a[mf], bb[ng][lo], bb[ng][2 + lo]);
                }
        }
    }

    __half* dst = g_w2h + (size_t)b * DIM * PKDIM + h * NA;
#pragma unroll
    for (int mf = 0; mf < 2; mf++) {
        const int r0 = mt * 128 + warp * 32 + mf * 16 + (lane >> 2);
        const int r8 = r0 + 8;
#pragma unroll
        for (int nf = 0; nf < 4; nf++) {
            const int c = nf * 8 + (lane & 3) * 2;
            *(__half2*)(dst + (size_t)r0 * PKDIM + c) = __floats2half2_rn(acc[mf][nf][0], acc[mf][nf][1]);
            *(__half2*)(dst + (size_t)r8 * PKDIM + c) = __floats2half2_rn(acc[mf][nf][2], acc[mf][nf][3]);
        }
    }
}

// ---------------- launch (single stream) ----------------
extern "C" void kernel_launch(void* const* d_in, const int* in_sizes, int n_in,
                              void* d_out, int out_size)
{
    const float* x    = (const float*)d_in[0];
    const float* ehs  = (const float*)d_in[1];
    const float* amap = (const float*)d_in[2];
    const float* q_w  = (const float*)d_in[3];
    const float* q_b  = (const float*)d_in[4];
    const float* kv_w = (const float*)d_in[5];
    const float* kv_b = (const float*)d_in[6];
    const float* p_w  = (const float*)d_in[7];
    const float* p_b  = (const float*)d_in[8];
    float* out = (float*)d_out;

    __half *xh, *qh, *qwh, *pwh, *ehsh, *kvwh, *probsh, *w2h;
    cudaGetSymbolAddress((void**)&xh,     g_xh);
    cudaGetSymbolAddress((void**)&qh,     g_qh);
    cudaGetSymbolAddress((void**)&qwh,    g_qwh);
    cudaGetSymbolAddress((void**)&pwh,    g_pwh);
    cudaGetSymbolAddress((void**)&ehsh,   g_ehsh);
    cudaGetSymbolAddress((void**)&kvwh,   g_kvwh);
    cudaGetSymbolAddress((void**)&probsh, g_probsh);
    cudaGetSymbolAddress((void**)&w2h,    g_w2h);

    cudaFuncSetAttribute((const void*)gemm_f16_small<true, true, false>,
                         cudaFuncAttributeMaxDynamicSharedMemorySize, SSM_TOT);
    cudaFuncSetAttribute((const void*)gemm_f16_small<false, false, false>,
                         cudaFuncAttributeMaxDynamicSharedMemorySize, SSM_TOT);
    cudaFuncSetAttribute((const void*)gemm_f16_small<false, false, true>,
                         cudaFuncAttributeMaxDynamicSharedMemorySize, SSM_TOT);

    // routing positions
    minmax_kernel<<<1, 512>>>(amap);
    pos_kernel<<<(N_TOK + 255) / 256, 256>>>(amap);

    // fp16 conversions (4x ILP)
    cvt_half_kernel<<<CVT_GRID(N_TOK * DIM / 4), 256>>>(x, xh, N_TOK * DIM / 4);
    cvt_half_kernel<<<CVT_GRID(DIM * DIM / 4), 256>>>(q_w, qwh, DIM * DIM / 4);
    cvt_half_kernel<<<CVT_GRID(DIM * DIM / 4), 256>>>(p_w, pwh, DIM * DIM / 4);
    cvt_half_kernel<<<CVT_GRID(KV_ROWS * ENC / 4), 256>>>(ehs, ehsh, KV_ROWS * ENC / 4);
    cvt_half_kernel<<<CVT_GRID(2 * DIM * ENC / 4), 256>>>(kv_w, kvwh, 2 * DIM * ENC / 4);

    // q = RoPE(x @ q_w^T + q_b) -> fp16
    gemm_f16_small<true, true, false><<<dim3(DIM / 128, (N_TOK + 127) / 128, 1), 256, SSM_TOT>>>(
        xh, qwh, q_b, qh, N_TOK, DIM, DIM, 0, 0, 0);

    // kv projection with fused split + RoPE(k): k -> fp32 g_k, v -> fp16 g_vh
    gemm_f16_small<false, false, true><<<dim3((2 * DIM) / 128, (KV_ROWS + 127) / 128, 1), 256, SSM_TOT>>>(
        ehsh, kvwh, kv_b, nullptr, KV_ROWS, 2 * DIM, ENC, 0, 0, 0);

    // attention probabilities
    attn_probs_kernel<<<dim3(NHEADS, N_T, 4), 256>>>();

    // W2 = V @ proj (tensor cores) -> fp16
    w2_mma_kernel<<<dim3(DIM / 128, NHEADS, N_T), 128>>>();

    // out[b] = probs[b] @ W2[b]^T + p_b   (batched, K=384)
    gemm_f16_small<false, false, false><<<dim3(DIM / 128, (S_SP + 127) / 128, N_T), 256, SSM_TOT>>>(
        probsh, w2h, p_b, out, S_SP, DIM, PKDIM,
        (size_t)S_SP * PKDIM, (size_t)DIM * PKDIM, (size_t)S_SP * DIM);
}

// round 14
// speedup vs baseline: 1.0653x; 1.0653x over previous
#include <cuda_runtime.h>
#include <cuda_fp16.h>
#include <cstdint>
#include <math.h>

// ---------------- fixed problem shapes ----------------
#define N_TOK   32760          // 21 * 1560
#define DIM     1536
#define NHEADS  12
#define HD      128
#define S_SP    1560
#define N_T     21
#define ENC     768
#define NA      32
#define KV_ROWS 672
#define PKDIM   384            // NHEADS * NA
#define LOG2_10000 13.287712379549449f

// ---------------- scratch ----------------
__device__ __half g_xh[N_TOK * DIM];          // fp16 x
__device__ __half g_qh[N_TOK * DIM];          // fp16 RoPE'd q
__device__ __half g_qwh[DIM * DIM];           // fp16 q_w
__device__ __half g_pwh[DIM * DIM];           // fp16 proj_w
__device__ __half g_ehsh[KV_ROWS * ENC];      // fp16 encoder states
__device__ __half g_kvwh[2 * DIM * ENC];      // fp16 kv_w
__device__ float  g_k[KV_ROWS * DIM];         // RoPE'd k (fp32)
__device__ __half g_vh[KV_ROWS * DIM];        // v (fp16)
__device__ __half g_probsh[N_TOK * PKDIM];    // softmax probs [t*S+s][h*32+a]
__device__ __half g_w2h[N_T * DIM * PKDIM];   // W2^T [b][c][h*32+a]
__device__ float  g_pos[N_TOK];
__device__ float  g_mm[4];

// ---------------- helpers ----------------
__device__ __forceinline__ uint32_t smem_u32(const void* p) {
    uint32_t r;
    asm("{.reg .u64 t; cvta.to.shared.u64 t, %1; cvt.u32.u64 %0, t;}" : "=r"(r) : "l"(p));
    return r;
}

#define LDSM4(r0, r1, r2, r3, addr)                                            \
    asm volatile("ldmatrix.sync.aligned.m8n8.x4.shared.b16 {%0,%1,%2,%3}, [%4];" \
                 : "=r"(r0), "=r"(r1), "=r"(r2), "=r"(r3) : "r"(addr))

#define MMA_F16(d, a, b0, b1)                                                  \
    asm volatile("mma.sync.aligned.m16n8k16.row.col.f32.f16.f16.f32 "           \
                 "{%0,%1,%2,%3},{%4,%5,%6,%7},{%8,%9},{%0,%1,%2,%3};"          \
                 : "+f"(d[0]), "+f"(d[1]), "+f"(d[2]), "+f"(d[3])              \
                 : "r"(a[0]), "r"(a[1]), "r"(a[2]), "r"(a[3]), "r"(b0), "r"(b1))

// ---------------- fp32 -> fp16 conversion (4x ILP) ----------------
__global__ void cvt_half_kernel(const float* __restrict__ in, __half* __restrict__ out, int n4) {
    int base = blockIdx.x * (blockDim.x * 4) + threadIdx.x;
    float4 v[4];
    bool ok[4];
#pragma unroll
    for (int g = 0; g < 4; g++) {
        int i = base + g * blockDim.x;
        ok[g] = (i < n4);
        if (ok[g]) v[g] = ((const float4*)in)[i];
    }
#pragma unroll
    for (int g = 0; g < 4; g++) {
        if (ok[g]) {
            int i = base + g * blockDim.x;
            __half2 h0 = __floats2half2_rn(v[g].x, v[g].y);
            __half2 h1 = __floats2half2_rn(v[g].z, v[g].w);
            uint2 pk;
            pk.x = *(uint32_t*)&h0;
            pk.y = *(uint32_t*)&h1;
            ((uint2*)out)[i] = pk;
        }
    }
}
#define CVT_GRID(n4) (((n4) + 1023) / 1024)

// ---------------- min/max of attn-map rows (single CTA, float4) ----------------
__global__ void minmax_kernel(const float* __restrict__ m) {
    __shared__ float s0[512], s1[512], s2[512], s3[512];
    int tid = threadIdx.x;
    float mn0 = 1e30f, mx0 = -1e30f, mn1 = 1e30f, mx1 = -1e30f;
    const float4* m0v = (const float4*)m;
    const float4* m1v = (const float4*)(m + N_TOK);
    for (int i = tid; i < N_TOK / 4; i += 512) {
        float4 v0 = m0v[i], v1 = m1v[i];
        mn0 = fminf(mn0, fminf(fminf(v0.x, v0.y), fminf(v0.z, v0.w)));
        mx0 = fmaxf(mx0, fmaxf(fmaxf(v0.x, v0.y), fmaxf(v0.z, v0.w)));
        mn1 = fminf(mn1, fminf(fminf(v1.x, v1.y), fminf(v1.z, v1.w)));
        mx1 = fmaxf(mx1, fmaxf(fmaxf(v1.x, v1.y), fmaxf(v1.z, v1.w)));
    }
    s0[tid] = mn0; s1[tid] = mx0; s2[tid] = mn1; s3[tid] = mx1;
    __syncthreads();
    for (int off = 256; off > 0; off >>= 1) {
        if (tid < off) {
            s0[tid] = fminf(s0[tid], s0[tid + off]);
            s1[tid] = fmaxf(s1[tid], s1[tid + off]);
            s2[tid] = fminf(s2[tid], s2[tid + off]);
            s3[tid] = fmaxf(s3[tid], s3[tid + off]);
        }
        __syncthreads();
    }
    if (tid == 0) { g_mm[0] = s0[0]; g_mm[1] = s1[0]; g_mm[2] = s2[0]; g_mm[3] = s3[0]; }
}

// ---------------- routing positions ----------------
__global__ void pos_kernel(const float* __restrict__ m) {
    int n = blockIdx.x * blockDim.x + threadIdx.x;
    if (n >= N_TOK) return;
    float m0 = m[n], m1 = m[N_TOK + n];
    float r;
    if (m0 >= m1) r = (m0 - g_mm[0]) / (g_mm[1] - g_mm[0] + 1e-8f) * 4.0f;
    else          r = (m1 - g_mm[2]) / (g_mm[3] - g_mm[2] + 1e-8f) * 4.0f + 20.0f;
    g_pos[n] = r;
}

// ======== fp16 GEMM: CTA 128x128, 3-stage, occ 2 (R12 mainloop) ========
#define KCHUNK  64
#define SSTAGES 3
#define SSM_SZ  16384
#define SSM_TOT (SSTAGES * 2 * SSM_SZ)          // 98304

__device__ __forceinline__ void fill_stage_s(
    const __half* __restrict__ A, const __half* __restrict__ B, int M, int K,
    int row0, int col0, int kt, uint32_t sA, uint32_t sB, int tid)
{
#pragma unroll
    for (int g = 0; g < 4; g++) {
        int ga = tid + g * 256;
        int row = ga >> 3, ch = ga & 7;
        uint32_t dst = sA + (uint32_t)row * 128u + (((uint32_t)ch * 16u) ^ (((uint32_t)row & 7u) << 4));
        const __half* src = A + (size_t)(row0 + row) * K + kt * KCHUNK + ch * 8;
        int sz = (row0 + row < M) ? 16 : 0;
        asm volatile("cp.async.cg.shared.global [%0], [%1], 16, %2;" :: "r"(dst), "l"(src), "r"(sz));
    }
#pragma unroll
    for (int g = 0; g < 4; g++) {
        int gb = tid + g * 256;
        int row = gb >> 3, ch = gb & 7;
        uint32_t dst = sB + (uint32_t)row * 128u + (((uint32_t)ch * 16u) ^ (((uint32_t)row & 7u) << 4));
        const __half* src = B + (size_t)(col0 + row) * K + kt * KCHUNK + ch * 8;
        asm volatile("cp.async.cg.shared.global [%0], [%1], 16;" :: "r"(dst), "l"(src));
    }
    asm volatile("cp.async.commit_group;");
}

// FUSE_ROPE: q epilogue (RoPE + fp16 out). KV_EPI: kv epilogue (RoPE k->fp32, v->fp16).
// otherwise: bias + (HALF_OUT ? fp16 : fp32) store.
template <bool FUSE_ROPE, bool HALF_OUT, bool KV_EPI>
__global__ void __launch_bounds__(256, 2) gemm_f16_small(
    const __half* __restrict__ A, const __half* __restrict__ B,
    const float* __restrict__ bias, void* __restrict__ Cv,
    int M, int N, int K, size_t strA, size_t strB, size_t strC)
{
    extern __shared__ float smem[];
    const int tid  = threadIdx.x;
    const int lane = tid & 31, warp = tid >> 5;
    const int wm = warp >> 2, wn = warp & 3;      // 2x4 warp grid, warp tile 64x32
    const int row0 = blockIdx.y * 128, col0 = blockIdx.x * 128;

    A += (size_t)blockIdx.z * strA;
    B += (size_t)blockIdx.z * strB;

    const uint32_t sA = smem_u32(smem);
    const uint32_t sB = sA + SSTAGES * SSM_SZ;
    const int ktiles = K / KCHUNK;

    fill_stage_s(A, B, M, K, row0, col0, 0, sA, sB, tid);
    fill_stage_s(A, B, M, K, row0, col0, 1, sA + SSM_SZ, sB + SSM_SZ, tid);

    float acc[4][4][4];
#pragma unroll
    for (int i = 0; i < 4; i++)
#pragma unroll
        for (int j = 0; j < 4; j++)
#pragma unroll
            for (int k = 0; k < 4; k++) acc[i][j][k] = 0.0f;

    const int aRow = wm * 64 + ((lane >> 3) & 1) * 8 + (lane & 7);
    const int bRow = wn * 32 + ((lane >> 3) & 1) * 8 + (lane & 7);
    const uint32_t colSel = ((lane >> 4) & 1) * 16;
    const uint32_t xorv = ((uint32_t)lane & 7u) << 4;

    for (int it = 0; it < ktiles; it++) {
        if (it < ktiles - 1) asm volatile("cp.async.wait_group 1;" ::: "memory");
        else                 asm volatile("cp.async.wait_group 0;" ::: "memory");
        __syncthreads();
        const int st = it % 3;
        const uint32_t bA = sA + st * SSM_SZ;
        const uint32_t bB = sB + st * SSM_SZ;
#pragma unroll
        for (int ks = 0; ks < 4; ks++) {
            uint32_t a[4][4], bb[2][4];
            const uint32_t cb = ((uint32_t)(ks * 32) + colSel) ^ xorv;
#pragma unroll
            for (int mf = 0; mf < 4; mf++) {
                uint32_t ad = bA + (uint32_t)(aRow + mf * 16) * 128 + cb;
                LDSM4(a[mf][0], a[mf][1], a[mf][2], a[mf][3], ad);
            }
#pragma unroll
            for (int ng = 0; ng < 2; ng++) {
                uint32_t bd = bB + (uint32_t)(bRow + ng * 16) * 128 + cb;
                LDSM4(bb[ng][0], bb[ng][1], bb[ng][2], bb[ng][3], bd);
            }
#pragma unroll
            for (int mf = 0; mf < 4; mf++)
#pragma unroll
                for (int nf = 0; nf < 4; nf++) {
                    const int ng = nf >> 1, lo = nf & 1;
                    MMA_F16(acc[mf][nf], a[mf], bb[ng][lo], bb[ng][2 + lo]);
                }
        }
        if (it + 2 < ktiles) {
            const int r = it + 2;
            fill_stage_s(A, B, M, K, row0, col0, r,
                         sA + (r % 3) * SSM_SZ, sB + (r % 3) * SSM_SZ, tid);
        }
    }

    // epilogue: c0,c1 at (row=lane>>2, col=2*(lane&3)); c2,c3 at row+8
#pragma unroll
    for (int mf = 0; mf < 4; mf++) {
        const int r0 = row0 + wm * 64 + mf * 16 + (lane >> 2);
        const int r8 = r0 + 8;
        float pos0 = 0.f, pos8 = 0.f;
        if (FUSE_ROPE) {
            pos0 = g_pos[(r0 < M) ? r0 : 0];
            pos8 = g_pos[(r8 < M) ? r8 : 0];
        }
        if (KV_EPI) {
            pos0 = ((r0 & 31) < 16) ? 2.0f : 22.0f;
            pos8 = ((r8 & 31) < 16) ? 2.0f : 22.0f;
        }
#pragma unroll
        for (int nf = 0; nf < 4; nf++) {
            const int c = col0 + wn * 32 + nf * 8 + (lane & 3) * 2;
            const float2 bv = *(const float2*)(bias + c);
            float o0 = acc[mf][nf][0] + bv.x;
            float o1 = acc[mf][nf][1] + bv.y;
            float o2 = acc[mf][nf][2] + bv.x;
            float o3 = acc[mf][nf][3] + bv.y;
            if (FUSE_ROPE || (KV_EPI && c < DIM)) {
                const int i = (c & 127) >> 1;   // RoPE pair index within the 128-d head
                const float fr = exp2f(-(float)i * (LOG2_10000 / 64.0f));
                float sn, cs;
                sincosf(pos0 * fr, &sn, &cs);
                float t0 = o0 * cs - o1 * sn;
                o1 = o1 * cs + o0 * sn; o0 = t0;
                sincosf(pos8 * fr, &sn, &cs);
                float t2 = o2 * cs - o3 * sn;
                o3 = o3 * cs + o2 * sn; o2 = t2;
            }
            if (KV_EPI) {
                if (c < DIM) {   // k half: fp32
                    if (r0 < M) *(float2*)(g_k + (size_t)r0 * DIM + c) = make_float2(o0, o1);
                    if (r8 < M) *(float2*)(g_k + (size_t)r8 * DIM + c) = make_float2(o2, o3);
                } else {         // v half: fp16
                    if (r0 < M) *(__half2*)(g_vh + (size_t)r0 * DIM + c - DIM) = __floats2half2_rn(o0, o1);
                    if (r8 < M) *(__half2*)(g_vh + (size_t)r8 * DIM + c - DIM) = __floats2half2_rn(o2, o3);
                }
            } else if (HALF_OUT) {
                __half* C = (__half*)Cv + (size_t)blockIdx.z * strC;
                if (r0 < M) *(__half2*)(C + (size_t)r0 * N + c) = __floats2half2_rn(o0, o1);
                if (r8 < M) *(__half2*)(C + (size_t)r8 * N + c) = __floats2half2_rn(o2, o3);
            } else {
                float* C = (float*)Cv + (size_t)blockIdx.z * strC;
                if (r0 < M) *(float2*)(C + (size_t)r0 * N + c) = make_float2(o0, o1);
                if (r8 < M) *(float2*)(C + (size_t)r8 * N + c) = make_float2(o2, o3);
            }
        }
    }
}

// ---------------- attention probs (float-staged q; s-split 4-way) ----------
#define S_CHUNK 390
__global__ void __launch_bounds__(256) attn_probs_kernel() {
    const int h = blockIdx.x;
    const int t = blockIdx.y;
    const int chunk = blockIdx.z;
    __shared__ float ks[32][132];
    __shared__ float qs[8][128];

    const int tid = threadIdx.x;
    for (int i = tid; i < 32 * 128; i += 256) {
        int a = i >> 7, d = i & 127;
        ks[a][d] = g_k[(size_t)(t * 32 + a) * DIM + h * HD + d];
    }
    __syncthreads();

    const int w = tid >> 5, l = tid & 31;
    const int sBeg = chunk * S_CHUNK;
    const int sEnd = (sBeg + S_CHUNK < S_SP) ? sBeg + S_CHUNK : S_SP;

    for (int s = sBeg + w; s < sEnd; s += 8) {
        size_t qoff = (size_t)(t * S_SP + s) * DIM + h * HD;
        uint2 qp = *(const uint2*)(g_qh + qoff + 4 * l);
        float2 f0 = __half22float2(*(__half2*)&qp.x);
        float2 f1 = __half22float2(*(__half2*)&qp.y);
        *(float4*)&qs[w][4 * l] = make_float4(f0.x, f0.y, f1.x, f1.y);
        __syncwarp();

        float acc = 0.0f;
        const float4* qr = (const float4*)&qs[w][0];
        const float4* kr = (const float4*)&ks[l][0];
#pragma unroll
        for (int j = 0; j < 32; j++) {
            float4 a4 = qr[j];
            float4 b4 = kr[j];
            acc += a4.x * b4.x + a4.y * b4.y + a4.z * b4.z + a4.w * b4.w;
        }
        acc *= 0.08838834764831845f;

        float mx = acc;
#pragma unroll
        for (int o = 16; o > 0; o >>= 1) mx = fmaxf(mx, __shfl_xor_sync(0xFFFFFFFFu, mx, o));
        float e = __expf(acc - mx);
        float sum = e;
#pragma unroll
        for (int o = 16; o > 0; o >>= 1) sum += __shfl_xor_sync(0xFFFFFFFFu, sum, o);
        float p = e / sum;

        g_probsh[(size_t)(t * S_SP + s) * PKDIM + h * NA + l] = __float2half_rn(p);
        __syncwarp();
    }
}

// ---------------- W2 fold on tensor cores ------------------------------------
__global__ void __launch_bounds__(128) w2_mma_kernel() {
    const int mt = blockIdx.x;
    const int h  = blockIdx.y;
    const int b  = blockIdx.z;
    __shared__ __align__(16) char smem[2 * 16384 + 2 * 4096];

    const int tid = threadIdx.x;
    const int lane = tid & 31, warp = tid >> 5;
    const uint32_t sA = smem_u32(smem);
    const uint32_t sB = sA + 2 * 16384;

#pragma unroll
    for (int g = 0; g < 16; g++) {
        int i = tid + g * 128;
        int kt = i >> 10, row = (i >> 3) & 127, ch = i & 7;
        uint32_t dst = sA + kt * 16384 + (uint32_t)row * 128u +
                       (((uint32_t)ch * 16u) ^ (((uint32_t)row & 7u) << 4));
        const __half* src = g_pwh + (size_t)(mt * 128 + row) * DIM + h * HD + kt * KCHUNK + ch * 8;
        asm volatile("cp.async.cg.shared.global [%0], [%1], 16;" :: "r"(dst), "l"(src));
    }
#pragma unroll
    for (int g = 0; g < 4; g++) {
        int i = tid + g * 128;
        int kt = i >> 8, row = (i >> 3) & 31, ch = i & 7;
        uint32_t dst = sB + kt * 4096 + (uint32_t)row * 128u +
                       (((uint32_t)ch * 16u) ^ (((uint32_t)row & 7u) << 4));
        const __half* src = g_vh + (size_t)(b * 32 + row) * DIM + h * HD + kt * KCHUNK + ch * 8;
        asm volatile("cp.async.cg.shared.global [%0], [%1], 16;" :: "r"(dst), "l"(src));
    }
    asm volatile("cp.async.commit_group;");
    asm volatile("cp.async.wait_group 0;" ::: "memory");
    __syncthreads();

    float acc[2][4][4];
#pragma unroll
    for (int i = 0; i < 2; i++)
#pragma unroll
        for (int j = 0; j < 4; j++)
#pragma unroll
            for (int k = 0; k < 4; k++) acc[i][j][k] = 0.0f;

    const int aRow = warp * 32 + ((lane >> 3) & 1) * 8 + (lane & 7);
    const int bRow = ((lane >> 3) & 1) * 8 + (lane & 7);
    const uint32_t colSel = ((lane >> 4) & 1) * 16;
    const uint32_t xorv = ((uint32_t)lane & 7u) << 4;

#pragma unroll
    for (int kt = 0; kt < 2; kt++) {
        const uint32_t bA = sA + kt * 16384;
        const uint32_t bB = sB + kt * 4096;
#pragma unroll
        for (int ks = 0; ks < 4; ks++) {
            uint32_t a[2][4], bb[2][4];
            const uint32_t cb = ((uint32_t)(ks * 32) + colSel) ^ xorv;
#pragma unroll
            for (int mf = 0; mf < 2; mf++) {
                uint32_t ad = bA + (uint32_t)(aRow + mf * 16) * 128 + cb;
                LDSM4(a[mf][0], a[mf][1], a[mf][2], a[mf][3], ad);
            }
#pragma unroll
            for (int ng = 0; ng < 2; ng++) {
                uint32_t bd = bB + (uint32_t)(bRow + ng * 16) * 128 + cb;
                LDSM4(bb[ng][0], bb[ng][1], bb[ng][2], bb[ng][3], bd);
            }
#pragma unroll
            for (int mf = 0; mf < 2; mf++)
#pragma unroll
                for (int nf = 0; nf < 4; nf++) {
                    const int ng = nf >> 1, lo = nf & 1;
                    MMA_F16(acc[mf][nf], a[mf], bb[ng][lo], bb[ng][2 + lo]);
                }
        }
    }

    __half* dst = g_w2h + (size_t)b * DIM * PKDIM + h * NA;
#pragma unroll
    for (int mf = 0; mf < 2; mf++) {
        const int r0 = mt * 128 + warp * 32 + mf * 16 + (lane >> 2);
        const int r8 = r0 + 8;
#pragma unroll
        for (int nf = 0; nf < 4; nf++) {
            const int c = nf * 8 + (lane & 3) * 2;
            *(__half2*)(dst + (size_t)r0 * PKDIM + c) = __floats2half2_rn(acc[mf][nf][0], acc[mf][nf][1]);
            *(__half2*)(dst + (size_t)r8 * PKDIM + c) = __floats2half2_rn(acc[mf][nf][2], acc[mf][nf][3]);
        }
    }
}

// ---------------- launch (single stream) ----------------
extern "C" void kernel_launch(void* const* d_in, const int* in_sizes, int n_in,
                              void* d_out, int out_size)
{
    const float* x    = (const float*)d_in[0];
    const float* ehs  = (const float*)d_in[1];
    const float* amap = (const float*)d_in[2];
    const float* q_w  = (const float*)d_in[3];
    const float* q_b  = (const float*)d_in[4];
    const float* kv_w = (const float*)d_in[5];
    const float* kv_b = (const float*)d_in[6];
    const float* p_w  = (const float*)d_in[7];
    const float* p_b  = (const float*)d_in[8];
    float* out = (float*)d_out;

    __half *xh, *qh, *qwh, *pwh, *ehsh, *kvwh, *probsh, *w2h;
    cudaGetSymbolAddress((void**)&xh,     g_xh);
    cudaGetSymbolAddress((void**)&qh,     g_qh);
    cudaGetSymbolAddress((void**)&qwh,    g_qwh);
    cudaGetSymbolAddress((void**)&pwh,    g_pwh);
    cudaGetSymbolAddress((void**)&ehsh,   g_ehsh);
    cudaGetSymbolAddress((void**)&kvwh,   g_kvwh);
    cudaGetSymbolAddress((void**)&probsh, g_probsh);
    cudaGetSymbolAddress((void**)&w2h,    g_w2h);

    cudaFuncSetAttribute((const void*)gemm_f16_small<true, true, false>,
                         cudaFuncAttributeMaxDynamicSharedMemorySize, SSM_TOT);
    cudaFuncSetAttribute((const void*)gemm_f16_small<false, false, false>,
                         cudaFuncAttributeMaxDynamicSharedMemorySize, SSM_TOT);
    cudaFuncSetAttribute((const void*)gemm_f16_small<false, false, true>,
                         cudaFuncAttributeMaxDynamicSharedMemorySize, SSM_TOT);

    // routing positions
    minmax_kernel<<<1, 512>>>(amap);
    pos_kernel<<<(N_TOK + 255) / 256, 256>>>(amap);

    // fp16 conversions (4x ILP)
    cvt_half_kernel<<<CVT_GRID(N_TOK * DIM / 4), 256>>>(x, xh, N_TOK * DIM / 4);
    cvt_half_kernel<<<CVT_GRID(DIM * DIM / 4), 256>>>(q_w, qwh, DIM * DIM / 4);
    cvt_half_kernel<<<CVT_GRID(DIM * DIM / 4), 256>>>(p_w, pwh, DIM * DIM / 4);
    cvt_half_kernel<<<CVT_GRID(KV_ROWS * ENC / 4), 256>>>(ehs, ehsh, KV_ROWS * ENC / 4);
    cvt_half_kernel<<<CVT_GRID(2 * DIM * ENC / 4), 256>>>(kv_w, kvwh, 2 * DIM * ENC / 4);

    // q = RoPE(x @ q_w^T + q_b) -> fp16
    gemm_f16_small<true, true, false><<<dim3(DIM / 128, (N_TOK + 127) / 128, 1), 256, SSM_TOT>>>(
        xh, qwh, q_b, qh, N_TOK, DIM, DIM, 0, 0, 0);

    // kv projection with fused split + RoPE(k): k -> fp32 g_k, v -> fp16 g_vh
    gemm_f16_small<false, false, true><<<dim3((2 * DIM) / 128, (KV_ROWS + 127) / 128, 1), 256, SSM_TOT>>>(
        ehsh, kvwh, kv_b, nullptr, KV_ROWS, 2 * DIM, ENC, 0, 0, 0);

    // attention probabilities
    attn_probs_kernel<<<dim3(NHEADS, N_T, 4), 256>>>();

    // W2 = V @ proj (tensor cores) -> fp16
    w2_mma_kernel<<<dim3(DIM / 128, NHEADS, N_T), 128>>>();

    // out[b] = probs[b] @ W2[b]^T + p_b   (batched, K=384)
    gemm_f16_small<false, false, false><<<dim3(DIM / 128, (S_SP + 127) / 128, N_T), 256, SSM_TOT>>>(
        probsh, w2h, p_b, out, S_SP, DIM, PKDIM,
        (size_t)S_SP * PKDIM, (size_t)DIM * PKDIM, (size_t)S_SP * DIM);
}

// round 15
// speedup vs baseline: 1.1208x; 1.0520x over previous
#include <cuda_runtime.h>
#include <cuda_fp16.h>
#include <cstdint>
#include <math.h>

// ---------------- fixed problem shapes ----------------
#define N_TOK   32760          // 21 * 1560
#define DIM     1536
#define NHEADS  12
#define HD      128
#define S_SP    1560
#define N_T     21
#define ENC     768
#define NA      32
#define KV_ROWS 672
#define PKDIM   384            // NHEADS * NA
#define LOG2_10000 13.287712379549449f

// ---------------- scratch ----------------
__device__ __half g_xh[N_TOK * DIM];          // fp16 x
__device__ __half g_qh[N_TOK * DIM];          // fp16 RoPE'd q
__device__ __half g_qwh[DIM * DIM];           // fp16 q_w
__device__ __half g_pwh[DIM * DIM];           // fp16 proj_w
__device__ __half g_ehsh[KV_ROWS * ENC];      // fp16 encoder states
__device__ __half g_kvwh[2 * DIM * ENC];      // fp16 kv_w
__device__ float  g_k[KV_ROWS * DIM];         // RoPE'd k (fp32)
__device__ __half g_vh[KV_ROWS * DIM];        // v (fp16)
__device__ __half g_probsh[N_TOK * PKDIM];    // softmax probs [t*S+s][h*32+a]
__device__ __half g_w2h[N_T * DIM * PKDIM];   // W2^T [b][c][h*32+a]
__device__ float  g_pos[N_TOK];
__device__ float  g_mm[4];

// ---------------- helpers ----------------
__device__ __forceinline__ uint32_t smem_u32(const void* p) {
    uint32_t r;
    asm("{.reg .u64 t; cvta.to.shared.u64 t, %1; cvt.u32.u64 %0, t;}" : "=r"(r) : "l"(p));
    return r;
}

#define LDSM4(r0, r1, r2, r3, addr)                                            \
    asm volatile("ldmatrix.sync.aligned.m8n8.x4.shared.b16 {%0,%1,%2,%3}, [%4];" \
                 : "=r"(r0), "=r"(r1), "=r"(r2), "=r"(r3) : "r"(addr))

#define MMA_F16(d, a, b0, b1)                                                  \
    asm volatile("mma.sync.aligned.m16n8k16.row.col.f32.f16.f16.f32 "           \
                 "{%0,%1,%2,%3},{%4,%5,%6,%7},{%8,%9},{%0,%1,%2,%3};"          \
                 : "+f"(d[0]), "+f"(d[1]), "+f"(d[2]), "+f"(d[3])              \
                 : "r"(a[0]), "r"(a[1]), "r"(a[2]), "r"(a[3]), "r"(b0), "r"(b1))

// ---------------- fp32 -> fp16 conversion (4x ILP; for x) ----------------
__global__ void cvt_half_kernel(const float* __restrict__ in, __half* __restrict__ out, int n4) {
    int base = blockIdx.x * (blockDim.x * 4) + threadIdx.x;
    float4 v[4];
    bool ok[4];
#pragma unroll
    for (int g = 0; g < 4; g++) {
        int i = base + g * blockDim.x;
        ok[g] = (i < n4);
        if (ok[g]) v[g] = ((const float4*)in)[i];
    }
#pragma unroll
    for (int g = 0; g < 4; g++) {
        if (ok[g]) {
            int i = base + g * blockDim.x;
            __half2 h0 = __floats2half2_rn(v[g].x, v[g].y);
            __half2 h1 = __floats2half2_rn(v[g].z, v[g].w);
            uint2 pk;
            pk.x = *(uint32_t*)&h0;
            pk.y = *(uint32_t*)&h1;
            ((uint2*)out)[i] = pk;
        }
    }
}
#define CVT_GRID(n4) (((n4) + 1023) / 1024)

// ---------------- fused conversion of the 4 small tensors -----------------
#define SEG0 589824                   // q_w  (DIM*DIM/4)
#define SEG1 1179648                  // + p_w
#define SEG2 1308672                  // + ehs (KV_ROWS*ENC/4)
#define SEG3 1898496                  // + kv_w (2*DIM*ENC/4)
__global__ void cvt_weights_kernel(const float* __restrict__ q_w, const float* __restrict__ p_w,
                                   const float* __restrict__ ehs, const float* __restrict__ kv_w) {
    int base = blockIdx.x * 1024 + threadIdx.x;
#pragma unroll
    for (int g = 0; g < 4; g++) {
        int i = base + g * 256;
        const float* src;
        __half* dst;
        int off;
        if (i < SEG0)      { src = q_w;  dst = g_qwh;  off = i; }
        else if (i < SEG1) { src = p_w;  dst = g_pwh;  off = i - SEG0; }
        else if (i < SEG2) { src = ehs;  dst = g_ehsh; off = i - SEG1; }
        else if (i < SEG3) { src = kv_w; dst = g_kvwh; off = i - SEG2; }
        else continue;
        float4 v = ((const float4*)src)[off];
        __half2 h0 = __floats2half2_rn(v.x, v.y);
        __half2 h1 = __floats2half2_rn(v.z, v.w);
        uint2 pk;
        pk.x = *(uint32_t*)&h0;
        pk.y = *(uint32_t*)&h1;
        ((uint2*)dst)[off] = pk;
    }
}

// ---------------- min/max of attn-map rows (single CTA, float4) ----------------
__global__ void minmax_kernel(const float* __restrict__ m) {
    __shared__ float s0[512], s1[512], s2[512], s3[512];
    int tid = threadIdx.x;
    float mn0 = 1e30f, mx0 = -1e30f, mn1 = 1e30f, mx1 = -1e30f;
    const float4* m0v = (const float4*)m;
    const float4* m1v = (const float4*)(m + N_TOK);
    for (int i = tid; i < N_TOK / 4; i += 512) {
        float4 v0 = m0v[i], v1 = m1v[i];
        mn0 = fminf(mn0, fminf(fminf(v0.x, v0.y), fminf(v0.z, v0.w)));
        mx0 = fmaxf(mx0, fmaxf(fmaxf(v0.x, v0.y), fmaxf(v0.z, v0.w)));
        mn1 = fminf(mn1, fminf(fminf(v1.x, v1.y), fminf(v1.z, v1.w)));
        mx1 = fmaxf(mx1, fmaxf(fmaxf(v1.x, v1.y), fmaxf(v1.z, v1.w)));
    }
    s0[tid] = mn0; s1[tid] = mx0; s2[tid] = mn1; s3[tid] = mx1;
    __syncthreads();
    for (int off = 256; off > 0; off >>= 1) {
        if (tid < off) {
            s0[tid] = fminf(s0[tid], s0[tid + off]);
            s1[tid] = fmaxf(s1[tid], s1[tid + off]);
            s2[tid] = fminf(s2[tid], s2[tid + off]);
            s3[tid] = fmaxf(s3[tid], s3[tid + off]);
        }
        __syncthreads();
    }
    if (tid == 0) { g_mm[0] = s0[0]; g_mm[1] = s1[0]; g_mm[2] = s2[0]; g_mm[3] = s3[0]; }
}

// ---------------- routing positions ----------------
__global__ void pos_kernel(const float* __restrict__ m) {
    int n = blockIdx.x * blockDim.x + threadIdx.x;
    if (n >= N_TOK) return;
    float m0 = m[n], m1 = m[N_TOK + n];
    float r;
    if (m0 >= m1) r = (m0 - g_mm[0]) / (g_mm[1] - g_mm[0] + 1e-8f) * 4.0f;
    else          r = (m1 - g_mm[2]) / (g_mm[3] - g_mm[2] + 1e-8f) * 4.0f + 20.0f;
    g_pos[n] = r;
}

// ======== fp16 GEMM: CTA 128x128, 3-stage, occ 2 ========
#define KCHUNK  64
#define SSTAGES 3
#define SSM_SZ  16384
#define SSM_TOT (SSTAGES * 2 * SSM_SZ)          // 98304

__device__ __forceinline__ void fill_stage_s(
    const __half* __restrict__ A, const __half* __restrict__ B, int M, int K,
    int row0, int col0, int kt, uint32_t sA, uint32_t sB, int tid)
{
#pragma unroll
    for (int g = 0; g < 4; g++) {
        int ga = tid + g * 256;
        int row = ga >> 3, ch = ga & 7;
        uint32_t dst = sA + (uint32_t)row * 128u + (((uint32_t)ch * 16u) ^ (((uint32_t)row & 7u) << 4));
        const __half* src = A + (size_t)(row0 + row) * K + kt * KCHUNK + ch * 8;
        int sz = (row0 + row < M) ? 16 : 0;
        asm volatile("cp.async.cg.shared.global [%0], [%1], 16, %2;" :: "r"(dst), "l"(src), "r"(sz));
    }
#pragma unroll
    for (int g = 0; g < 4; g++) {
        int gb = tid + g * 256;
        int row = gb >> 3, ch = gb & 7;
        uint32_t dst = sB + (uint32_t)row * 128u + (((uint32_t)ch * 16u) ^ (((uint32_t)row & 7u) << 4));
        const __half* src = B + (size_t)(col0 + row) * K + kt * KCHUNK + ch * 8;
        asm volatile("cp.async.cg.shared.global [%0], [%1], 16;" :: "r"(dst), "l"(src));
    }
    asm volatile("cp.async.commit_group;");
}

// FUSE_ROPE: q epilogue (RoPE + fp16 out). KV_EPI: kv epilogue (RoPE k->fp32, v->fp16).
template <bool FUSE_ROPE, bool HALF_OUT, bool KV_EPI>
__global__ void __launch_bounds__(256, 2) gemm_f16_small(
    const __half* __restrict__ A, const __half* __restrict__ B,
    const float* __restrict__ bias, void* __restrict__ Cv,
    int M, int N, int K, size_t strA, size_t strB, size_t strC)
{
    extern __shared__ float smem[];
    const int tid  = threadIdx.x;
    const int lane = tid & 31, warp = tid >> 5;
    const int wm = warp >> 2, wn = warp & 3;      // 2x4 warp grid, warp tile 64x32
    const int row0 = blockIdx.y * 128, col0 = blockIdx.x * 128;

    A += (size_t)blockIdx.z * strA;
    B += (size_t)blockIdx.z * strB;

    const uint32_t sA = smem_u32(smem);
    const uint32_t sB = sA + SSTAGES * SSM_SZ;
    const int ktiles = K / KCHUNK;

    fill_stage_s(A, B, M, K, row0, col0, 0, sA, sB, tid);
    fill_stage_s(A, B, M, K, row0, col0, 1, sA + SSM_SZ, sB + SSM_SZ, tid);

    float acc[4][4][4];
#pragma unroll
    for (int i = 0; i < 4; i++)
#pragma unroll
        for (int j = 0; j < 4; j++)
#pragma unroll
            for (int k = 0; k < 4; k++) acc[i][j][k] = 0.0f;

    const int aRow = wm * 64 + ((lane >> 3) & 1) * 8 + (lane & 7);
    const int bRow = wn * 32 + ((lane >> 3) & 1) * 8 + (lane & 7);
    const uint32_t colSel = ((lane >> 4) & 1) * 16;
    const uint32_t xorv = ((uint32_t)lane & 7u) << 4;

    for (int it = 0; it < ktiles; it++) {
        if (it < ktiles - 1) asm volatile("cp.async.wait_group 1;" ::: "memory");
        else                 asm volatile("cp.async.wait_group 0;" ::: "memory");
        __syncthreads();
        const int st = it % 3;
        const uint32_t bA = sA + st * SSM_SZ;
        const uint32_t bB = sB + st * SSM_SZ;
        // issue next prefetch BEFORE compute: barrier above already guarantees
        // stage (it+2)%3's previous consumers are done; groups retire in order
        // so wait_group counts are unchanged.
        if (it + 2 < ktiles) {
            const int r = it + 2;
            fill_stage_s(A, B, M, K, row0, col0, r,
                         sA + (r % 3) * SSM_SZ, sB + (r % 3) * SSM_SZ, tid);
        }
#pragma unroll
        for (int ks = 0; ks < 4; ks++) {
            uint32_t a[4][4], bb[2][4];
            const uint32_t cb = ((uint32_t)(ks * 32) + colSel) ^ xorv;
#pragma unroll
            for (int mf = 0; mf < 4; mf++) {
                uint32_t ad = bA + (uint32_t)(aRow + mf * 16) * 128 + cb;
                LDSM4(a[mf][0], a[mf][1], a[mf][2], a[mf][3], ad);
            }
#pragma unroll
            for (int ng = 0; ng < 2; ng++) {
                uint32_t bd = bB + (uint32_t)(bRow + ng * 16) * 128 + cb;
                LDSM4(bb[ng][0], bb[ng][1], bb[ng][2], bb[ng][3], bd);
            }
#pragma unroll
            for (int mf = 0; mf < 4; mf++)
#pragma unroll
                for (int nf = 0; nf < 4; nf++) {
                    const int ng = nf >> 1, lo = nf & 1;
                    MMA_F16(acc[mf][nf], a[mf], bb[ng][lo], bb[ng][2 + lo]);
                }
        }
    }

    // epilogue: c0,c1 at (row=lane>>2, col=2*(lane&3)); c2,c3 at row+8
#pragma unroll
    for (int mf = 0; mf < 4; mf++) {
        const int r0 = row0 + wm * 64 + mf * 16 + (lane >> 2);
        const int r8 = r0 + 8;
        float pos0 = 0.f, pos8 = 0.f;
        if (FUSE_ROPE) {
            pos0 = g_pos[(r0 < M) ? r0 : 0];
            pos8 = g_pos[(r8 < M) ? r8 : 0];
        }
        if (KV_EPI) {
            pos0 = ((r0 & 31) < 16) ? 2.0f : 22.0f;
            pos8 = ((r8 & 31) < 16) ? 2.0f : 22.0f;
        }
#pragma unroll
        for (int nf = 0; nf < 4; nf++) {
            const int c = col0 + wn * 32 + nf * 8 + (lane & 3) * 2;
            const float2 bv = *(const float2*)(bias + c);
            float o0 = acc[mf][nf][0] + bv.x;
            float o1 = acc[mf][nf][1] + bv.y;
            float o2 = acc[mf][nf][2] + bv.x;
            float o3 = acc[mf][nf][3] + bv.y;
            if (FUSE_ROPE || (KV_EPI && c < DIM)) {
                const int i = (c & 127) >> 1;   // RoPE pair index within the 128-d head
                const float fr = exp2f(-(float)i * (LOG2_10000 / 64.0f));
                float sn, cs;
                sincosf(pos0 * fr, &sn, &cs);
                float t0 = o0 * cs - o1 * sn;
                o1 = o1 * cs + o0 * sn; o0 = t0;
                sincosf(pos8 * fr, &sn, &cs);
                float t2 = o2 * cs - o3 * sn;
                o3 = o3 * cs + o2 * sn; o2 = t2;
            }
            if (KV_EPI) {
                if (c < DIM) {   // k half: fp32
                    if (r0 < M) *(float2*)(g_k + (size_t)r0 * DIM + c) = make_float2(o0, o1);
                    if (r8 < M) *(float2*)(g_k + (size_t)r8 * DIM + c) = make_float2(o2, o3);
                } else {         // v half: fp16
                    if (r0 < M) *(__half2*)(g_vh + (size_t)r0 * DIM + c - DIM) = __floats2half2_rn(o0, o1);
                    if (r8 < M) *(__half2*)(g_vh + (size_t)r8 * DIM + c - DIM) = __floats2half2_rn(o2, o3);
                }
            } else if (HALF_OUT) {
                __half* C = (__half*)Cv + (size_t)blockIdx.z * strC;
                if (r0 < M) *(__half2*)(C + (size_t)r0 * N + c) = __floats2half2_rn(o0, o1);
                if (r8 < M) *(__half2*)(C + (size_t)r8 * N + c) = __floats2half2_rn(o2, o3);
            } else {
                float* C = (float*)Cv + (size_t)blockIdx.z * strC;
                if (r0 < M) *(float2*)(C + (size_t)r0 * N + c) = make_float2(o0, o1);
                if (r8 < M) *(float2*)(C + (size_t)r8 * N + c) = make_float2(o2, o3);
            }
        }
    }
}

// ---------------- attention probs: 2 rows/warp/iter, 4 partial accumulators ----
#define S_CHUNK 390
__global__ void __launch_bounds__(256) attn_probs_kernel() {
    const int h = blockIdx.x;
    const int t = blockIdx.y;
    const int chunk = blockIdx.z;
    __shared__ float ks[32][132];
    __shared__ float qs[8][2][128];

    const int tid = threadIdx.x;
    for (int i = tid; i < 32 * 128; i += 256) {
        int a = i >> 7, d = i & 127;
        ks[a][d] = g_k[(size_t)(t * 32 + a) * DIM + h * HD + d];
    }
    __syncthreads();

    const int w = tid >> 5, l = tid & 31;
    const int sBeg = chunk * S_CHUNK;
    const int sEnd = (sBeg + S_CHUNK < S_SP) ? sBeg + S_CHUNK : S_SP;

    for (int s0 = sBeg + 2 * w; s0 < sEnd; s0 += 16) {
        const int s1 = s0 + 1;
        const bool ok1 = (s1 < sEnd);
        // stage both q rows as float
        {
            size_t qoff = (size_t)(t * S_SP + s0) * DIM + h * HD;
            uint2 qp = *(const uint2*)(g_qh + qoff + 4 * l);
            float2 f0 = __half22float2(*(__half2*)&qp.x);
            float2 f1 = __half22float2(*(__half2*)&qp.y);
            *(float4*)&qs[w][0][4 * l] = make_float4(f0.x, f0.y, f1.x, f1.y);
        }
        if (ok1) {
            size_t qoff = (size_t)(t * S_SP + s1) * DIM + h * HD;
            uint2 qp = *(const uint2*)(g_qh + qoff + 4 * l);
            float2 f0 = __half22float2(*(__half2*)&qp.x);
            float2 f1 = __half22float2(*(__half2*)&qp.y);
            *(float4*)&qs[w][1][4 * l] = make_float4(f0.x, f0.y, f1.x, f1.y);
        }
        __syncwarp();

        // two dots, 4 partial accumulators each (breaks the FFMA chain)
        float p0a = 0.f, p0b = 0.f, p0c = 0.f, p0d = 0.f;
        float p1a = 0.f, p1b = 0.f, p1c = 0.f, p1d = 0.f;
        const float4* q0 = (const float4*)&qs[w][0][0];
        const float4* q1 = (const float4*)&qs[w][1][0];
        const float4* kr = (const float4*)&ks[l][0];
#pragma unroll
        for (int j = 0; j < 32; j += 4) {
            float4 k0 = kr[j], k1 = kr[j + 1], k2 = kr[j + 2], k3 = kr[j + 3];
            float4 a0 = q0[j], a1 = q0[j + 1], a2 = q0[j + 2], a3 = q0[j + 3];
            p0a += a0.x * k0.x + a0.y * k0.y + a0.z * k0.z + a0.w * k0.w;
            p0b += a1.x * k1.x + a1.y * k1.y + a1.z * k1.z + a1.w * k1.w;
            p0c += a2.x * k2.x + a2.y * k2.y + a2.z * k2.z + a2.w * k2.w;
            p0d += a3.x * k3.x + a3.y * k3.y + a3.z * k3.z + a3.w * k3.w;
            float4 b0 = q1[j], b1 = q1[j + 1], b2 = q1[j + 2], b3 = q1[j + 3];
            p1a += b0.x * k0.x + b0.y * k0.y + b0.z * k0.z + b0.w * k0.w;
            p1b += b1.x * k1.x + b1.y * k1.y + b1.z * k1.z + b1.w * k1.w;
            p1c += b2.x * k2.x + b2.y * k2.y + b2.z * k2.z + b2.w * k2.w;
            p1d += b3.x * k3.x + b3.y * k3.y + b3.z * k3.z + b3.w * k3.w;
        }
        float acc0 = ((p0a + p0b) + (p0c + p0d)) * 0.08838834764831845f;
        float acc1 = ((p1a + p1b) + (p1c + p1d)) * 0.08838834764831845f;

        // interleaved softmax reductions across the 32 lanes (keys)
        float mx0 = acc0, mx1 = acc1;
#pragma unroll
        for (int o = 16; o > 0; o >>= 1) {
            mx0 = fmaxf(mx0, __shfl_xor_sync(0xFFFFFFFFu, mx0, o));
            mx1 = fmaxf(mx1, __shfl_xor_sync(0xFFFFFFFFu, mx1, o));
        }
        float e0 = __expf(acc0 - mx0);
        float e1 = __expf(acc1 - mx1);
        float sm0 = e0, sm1 = e1;
#pragma unroll
        for (int o = 16; o > 0; o >>= 1) {
            sm0 += __shfl_xor_sync(0xFFFFFFFFu, sm0, o);
            sm1 += __shfl_xor_sync(0xFFFFFFFFu, sm1, o);
        }
        g_probsh[(size_t)(t * S_SP + s0) * PKDIM + h * NA + l] = __float2half_rn(e0 / sm0);
        if (ok1)
            g_probsh[(size_t)(t * S_SP + s1) * PKDIM + h * NA + l] = __float2half_rn(e1 / sm1);
        __syncwarp();
    }
}

// ---------------- W2 fold on tensor cores ------------------------------------
__global__ void __launch_bounds__(128) w2_mma_kernel() {
    const int mt = blockIdx.x;
    const int h  = blockIdx.y;
    const int b  = blockIdx.z;
    __shared__ __align__(16) char smem[2 * 16384 + 2 * 4096];

    const int tid = threadIdx.x;
    const int lane = tid & 31, warp = tid >> 5;
    const uint32_t sA = smem_u32(smem);
    const uint32_t sB = sA + 2 * 16384;

#pragma unroll
    for (int g = 0; g < 16; g++) {
        int i = tid + g * 128;
        int kt = i >> 10, row = (i >> 3) & 127, ch = i & 7;
        uint32_t dst = sA + kt * 16384 + (uint32_t)row * 128u +
                       (((uint32_t)ch * 16u) ^ (((uint32_t)row & 7u) << 4));
        const __half* src = g_pwh + (size_t)(mt * 128 + row) * DIM + h * HD + kt * KCHUNK + ch * 8;
        asm volatile("cp.async.cg.shared.global [%0], [%1], 16;" :: "r"(dst), "l"(src));
    }
#pragma unroll
    for (int g = 0; g < 4; g++) {
        int i = tid + g * 128;
        int kt = i >> 8, row = (i >> 3) & 31, ch = i & 7;
        uint32_t dst = sB + kt * 4096 + (uint32_t)row * 128u +
                       (((uint32_t)ch * 16u) ^ (((uint32_t)row & 7u) << 4));
        const __half* src = g_vh + (size_t)(b * 32 + row) * DIM + h * HD + kt * KCHUNK + ch * 8;
        asm volatile("cp.async.cg.shared.global [%0], [%1], 16;" :: "r"(dst), "l"(src));
    }
    asm volatile("cp.async.commit_group;");
    asm volatile("cp.async.wait_group 0;" ::: "memory");
    __syncthreads();

    float acc[2][4][4];
#pragma unroll
    for (int i = 0; i < 2; i++)
#pragma unroll
        for (int j = 0; j < 4; j++)
#pragma unroll
            for (int k = 0; k < 4; k++) acc[i][j][k] = 0.0f;

    const int aRow = warp * 32 + ((lane >> 3) & 1) * 8 + (lane & 7);
    const int bRow = ((lane >> 3) & 1) * 8 + (lane & 7);
    const uint32_t colSel = ((lane >> 4) & 1) * 16;
    const uint32_t xorv = ((uint32_t)lane & 7u) << 4;

#pragma unroll
    for (int kt = 0; kt < 2; kt++) {
        const uint32_t bA = sA + kt * 16384;
        const uint32_t bB = sB + kt * 4096;
#pragma unroll
        for (int ks = 0; ks < 4; ks++) {
            uint32_t a[2][4], bb[2][4];
            const uint32_t cb = ((uint32_t)(ks * 32) + colSel) ^ xorv;
#pragma unroll
            for (int mf = 0; mf < 2; mf++) {
                uint32_t ad = bA + (uint32_t)(aRow + mf * 16) * 128 + cb;
                LDSM4(a[mf][0], a[mf][1], a[mf][2], a[mf][3], ad);
            }
#pragma unroll
            for (int ng = 0; ng < 2; ng++) {
                uint32_t bd = bB + (uint32_t)(bRow + ng * 16) * 128 + cb;
                LDSM4(bb[ng][0], bb[ng][1], bb[ng][2], bb[ng][3], bd);
            }
#pragma unroll
            for (int mf = 0; mf < 2; mf++)
#pragma unroll
                for (int nf = 0; nf < 4; nf++) {
                    const int ng = nf >> 1, lo = nf & 1;
                    MMA_F16(acc[mf][nf], a[mf], bb[ng][lo], bb[ng][2 + lo]);
                }
        }
    }

    __half* dst = g_w2h + (size_t)b * DIM * PKDIM + h * NA;
#pragma unroll
    for (int mf = 0; mf < 2; mf++) {
        const int r0 = mt * 128 + warp * 32 + mf * 16 + (lane >> 2);
        const int r8 = r0 + 8;
#pragma unroll
        for (int nf = 0; nf < 4; nf++) {
            const int c = nf * 8 + (lane & 3) * 2;
            *(__half2*)(dst + (size_t)r0 * PKDIM + c) = __floats2half2_rn(acc[mf][nf][0], acc[mf][nf][1]);
            *(__half2*)(dst + (size_t)r8 * PKDIM + c) = __floats2half2_rn(acc[mf][nf][2], acc[mf][nf][3]);
        }
    }
}

// ---------------- launch (single stream) ----------------
extern "C" void kernel_launch(void* const* d_in, const int* in_sizes, int n_in,
                              void* d_out, int out_size)
{
    const float* x    = (const float*)d_in[0];
    const float* ehs  = (const float*)d_in[1];
    const float* amap = (const float*)d_in[2];
    const float* q_w  = (const float*)d_in[3];
    const float* q_b  = (const float*)d_in[4];
    const float* kv_w = (const float*)d_in[5];
    const float* kv_b = (const float*)d_in[6];
    const float* p_w  = (const float*)d_in[7];
    const float* p_b  = (const float*)d_in[8];
    float* out = (float*)d_out;

    __half *xh, *qh, *qwh, *kvwh, *probsh, *w2h;
    cudaGetSymbolAddress((void**)&xh,     g_xh);
    cudaGetSymbolAddress((void**)&qh,     g_qh);
    cudaGetSymbolAddress((void**)&qwh,    g_qwh);
    cudaGetSymbolAddress((void**)&kvwh,   g_kvwh);
    cudaGetSymbolAddress((void**)&probsh, g_probsh);
    cudaGetSymbolAddress((void**)&w2h,    g_w2h);
    __half* ehsh;
    cudaGetSymbolAddress((void**)&ehsh,   g_ehsh);

    cudaFuncSetAttribute((const void*)gemm_f16_small<true, true, false>,
                         cudaFuncAttributeMaxDynamicSharedMemorySize, SSM_TOT);
    cudaFuncSetAttribute((const void*)gemm_f16_small<false, false, false>,
                         cudaFuncAttributeMaxDynamicSharedMemorySize, SSM_TOT);
    cudaFuncSetAttribute((const void*)gemm_f16_small<false, false, true>,
                         cudaFuncAttributeMaxDynamicSharedMemorySize, SSM_TOT);

    // routing positions
    minmax_kernel<<<1, 512>>>(amap);
    pos_kernel<<<(N_TOK + 255) / 256, 256>>>(amap);

    // fp16 conversions
    cvt_half_kernel<<<CVT_GRID(N_TOK * DIM / 4), 256>>>(x, xh, N_TOK * DIM / 4);
    cvt_weights_kernel<<<(SEG3 + 1023) / 1024, 256>>>(q_w, p_w, ehs, kv_w);

    // q = RoPE(x @ q_w^T + q_b) -> fp16
    gemm_f16_small<true, true, false><<<dim3(DIM / 128, (N_TOK + 127) / 128, 1), 256, SSM_TOT>>>(
        xh, qwh, q_b, qh, N_TOK, DIM, DIM, 0, 0, 0);

    // kv projection with fused split + RoPE(k): k -> fp32 g_k, v -> fp16 g_vh
    gemm_f16_small<false, false, true><<<dim3((2 * DIM) / 128, (KV_ROWS + 127) / 128, 1), 256, SSM_TOT>>>(
        ehsh, kvwh, kv_b, nullptr, KV_ROWS, 2 * DIM, ENC, 0, 0, 0);

    // attention probabilities
    attn_probs_kernel<<<dim3(NHEADS, N_T, 4), 256>>>();

    // W2 = V @ proj (tensor cores) -> fp16
    w2_mma_kernel<<<dim3(DIM / 128, NHEADS, N_T), 128>>>();

    // out[b] = probs[b] @ W2[b]^T + p_b   (batched, K=384)
    gemm_f16_small<false, false, false><<<dim3(DIM / 128, (S_SP + 127) / 128, N_T), 256, SSM_TOT>>>(
        probsh, w2h, p_b, out, S_SP, DIM, PKDIM,
        (size_t)S_SP * PKDIM, (size_t)DIM * PKDIM, (size_t)S_SP * DIM);
}

// round 16
// speedup vs baseline: 1.4829x; 1.3231x over previous
#include <cuda_runtime.h>
#include <cuda_fp16.h>
#include <cstdint>
#include <math.h>

// ---------------- fixed problem shapes ----------------
#define N_TOK   32760          // 21 * 1560
#define DIM     1536
#define NHEADS  12
#define HD      128
#define S_SP    1560
#define N_T     21
#define ENC     768
#define NA      32
#define KV_ROWS 672
#define PKDIM   384            // NHEADS * NA
#define LOG2_10000 13.287712379549449f

// ---------------- scratch ----------------
__device__ __half g_xh[N_TOK * DIM];          // fp16 x
__device__ __half g_qwh[DIM * DIM];           // fp16 q_w
__device__ __half g_pwh[DIM * DIM];           // fp16 proj_w
__device__ __half g_ehsh[KV_ROWS * ENC];      // fp16 encoder states
__device__ __half g_kvwh[2 * DIM * ENC];      // fp16 kv_w
__device__ __half g_kh[KV_ROWS * DIM];        // RoPE'd k (fp16)
__device__ __half g_vh[KV_ROWS * DIM];        // v (fp16)
__device__ __half g_probsh[N_TOK * PKDIM];    // softmax probs [t*S+s][h*32+a]
__device__ __half g_w2h[N_T * DIM * PKDIM];   // W2^T [b][c][h*32+a]
__device__ float  g_pos[N_TOK];
__device__ float  g_mm[4];

// ---------------- helpers ----------------
__device__ __forceinline__ uint32_t smem_u32(const void* p) {
    uint32_t r;
    asm("{.reg .u64 t; cvta.to.shared.u64 t, %1; cvt.u32.u64 %0, t;}" : "=r"(r) : "l"(p));
    return r;
}

#define LDSM4(r0, r1, r2, r3, addr)                                            \
    asm volatile("ldmatrix.sync.aligned.m8n8.x4.shared.b16 {%0,%1,%2,%3}, [%4];" \
                 : "=r"(r0), "=r"(r1), "=r"(r2), "=r"(r3) : "r"(addr))

#define MMA_F16(d, a, b0, b1)                                                  \
    asm volatile("mma.sync.aligned.m16n8k16.row.col.f32.f16.f16.f32 "           \
                 "{%0,%1,%2,%3},{%4,%5,%6,%7},{%8,%9},{%0,%1,%2,%3};"          \
                 : "+f"(d[0]), "+f"(d[1]), "+f"(d[2]), "+f"(d[3])              \
                 : "r"(a[0]), "r"(a[1]), "r"(a[2]), "r"(a[3]), "r"(b0), "r"(b1))

// ---------------- fp32 -> fp16 conversion (4x ILP; for x) ----------------
__global__ void cvt_half_kernel(const float* __restrict__ in, __half* __restrict__ out, int n4) {
    int base = blockIdx.x * (blockDim.x * 4) + threadIdx.x;
    float4 v[4];
    bool ok[4];
#pragma unroll
    for (int g = 0; g < 4; g++) {
        int i = base + g * blockDim.x;
        ok[g] = (i < n4);
        if (ok[g]) v[g] = ((const float4*)in)[i];
    }
#pragma unroll
    for (int g = 0; g < 4; g++) {
        if (ok[g]) {
            int i = base + g * blockDim.x;
            __half2 h0 = __floats2half2_rn(v[g].x, v[g].y);
            __half2 h1 = __floats2half2_rn(v[g].z, v[g].w);
            uint2 pk;
            pk.x = *(uint32_t*)&h0;
            pk.y = *(uint32_t*)&h1;
            ((uint2*)out)[i] = pk;
        }
    }
}
#define CVT_GRID(n4) (((n4) + 1023) / 1024)

// ---------------- fused conversion of the 4 small tensors -----------------
#define SEG0 589824                   // q_w  (DIM*DIM/4)
#define SEG1 1179648                  // + p_w
#define SEG2 1308672                  // + ehs (KV_ROWS*ENC/4)
#define SEG3 1898496                  // + kv_w (2*DIM*ENC/4)
__global__ void cvt_weights_kernel(const float* __restrict__ q_w, const float* __restrict__ p_w,
                                   const float* __restrict__ ehs, const float* __restrict__ kv_w) {
    int base = blockIdx.x * 1024 + threadIdx.x;
#pragma unroll
    for (int g = 0; g < 4; g++) {
        int i = base + g * 256;
        const float* src;
        __half* dst;
        int off;
        if (i < SEG0)      { src = q_w;  dst = g_qwh;  off = i; }
        else if (i < SEG1) { src = p_w;  dst = g_pwh;  off = i - SEG0; }
        else if (i < SEG2) { src = ehs;  dst = g_ehsh; off = i - SEG1; }
        else if (i < SEG3) { src = kv_w; dst = g_kvwh; off = i - SEG2; }
        else continue;
        float4 v = ((const float4*)src)[off];
        __half2 h0 = __floats2half2_rn(v.x, v.y);
        __half2 h1 = __floats2half2_rn(v.z, v.w);
        uint2 pk;
        pk.x = *(uint32_t*)&h0;
        pk.y = *(uint32_t*)&h1;
        ((uint2*)dst)[off] = pk;
    }
}

// ---------------- min/max of attn-map rows (single CTA, float4) ----------------
__global__ void minmax_kernel(const float* __restrict__ m) {
    __shared__ float s0[512], s1[512], s2[512], s3[512];
    int tid = threadIdx.x;
    float mn0 = 1e30f, mx0 = -1e30f, mn1 = 1e30f, mx1 = -1e30f;
    const float4* m0v = (const float4*)m;
    const float4* m1v = (const float4*)(m + N_TOK);
    for (int i = tid; i < N_TOK / 4; i += 512) {
        float4 v0 = m0v[i], v1 = m1v[i];
        mn0 = fminf(mn0, fminf(fminf(v0.x, v0.y), fminf(v0.z, v0.w)));
        mx0 = fmaxf(mx0, fmaxf(fmaxf(v0.x, v0.y), fmaxf(v0.z, v0.w)));
        mn1 = fminf(mn1, fminf(fminf(v1.x, v1.y), fminf(v1.z, v1.w)));
        mx1 = fmaxf(mx1, fmaxf(fmaxf(v1.x, v1.y), fmaxf(v1.z, v1.w)));
    }
    s0[tid] = mn0; s1[tid] = mx0; s2[tid] = mn1; s3[tid] = mx1;
    __syncthreads();
    for (int off = 256; off > 0; off >>= 1) {
        if (tid < off) {
            s0[tid] = fminf(s0[tid], s0[tid + off]);
            s1[tid] = fmaxf(s1[tid], s1[tid + off]);
            s2[tid] = fminf(s2[tid], s2[tid + off]);
            s3[tid] = fmaxf(s3[tid], s3[tid + off]);
        }
        __syncthreads();
    }
    if (tid == 0) { g_mm[0] = s0[0]; g_mm[1] = s1[0]; g_mm[2] = s2[0]; g_mm[3] = s3[0]; }
}

// ---------------- routing positions ----------------
__global__ void pos_kernel(const float* __restrict__ m) {
    int n = blockIdx.x * blockDim.x + threadIdx.x;
    if (n >= N_TOK) return;
    float m0 = m[n], m1 = m[N_TOK + n];
    float r;
    if (m0 >= m1) r = (m0 - g_mm[0]) / (g_mm[1] - g_mm[0] + 1e-8f) * 4.0f;
    else          r = (m1 - g_mm[2]) / (g_mm[3] - g_mm[2] + 1e-8f) * 4.0f + 20.0f;
    g_pos[n] = r;
}

// ======== fp16 GEMM: CTA 128x128, 3-stage, occ 2 ========
#define KCHUNK  64
#define SSTAGES 3
#define SSM_SZ  16384
#define SSM_TOT (SSTAGES * 2 * SSM_SZ)          // 98304

__device__ __forceinline__ void fill_stage_s(
    const __half* __restrict__ A, const __half* __restrict__ B, int M, int K,
    int row0, int col0, int kt, uint32_t sA, uint32_t sB, int tid)
{
#pragma unroll
    for (int g = 0; g < 4; g++) {
        int ga = tid + g * 256;
        int row = ga >> 3, ch = ga & 7;
        uint32_t dst = sA + (uint32_t)row * 128u + (((uint32_t)ch * 16u) ^ (((uint32_t)row & 7u) << 4));
        const __half* src = A + (size_t)(row0 + row) * K + kt * KCHUNK + ch * 8;
        int sz = (row0 + row < M) ? 16 : 0;
        asm volatile("cp.async.cg.shared.global [%0], [%1], 16, %2;" :: "r"(dst), "l"(src), "r"(sz));
    }
#pragma unroll
    for (int g = 0; g < 4; g++) {
        int gb = tid + g * 256;
        int row = gb >> 3, ch = gb & 7;
        uint32_t dst = sB + (uint32_t)row * 128u + (((uint32_t)ch * 16u) ^ (((uint32_t)row & 7u) << 4));
        const __half* src = B + (size_t)(col0 + row) * K + kt * KCHUNK + ch * 8;
        asm volatile("cp.async.cg.shared.global [%0], [%1], 16;" :: "r"(dst), "l"(src));
    }
    asm volatile("cp.async.commit_group;");
}

// Generic GEMM (kv projection with fused RoPE split, final GEMM).
template <bool HALF_OUT, bool KV_EPI>
__global__ void __launch_bounds__(256, 2) gemm_f16_small(
    const __half* __restrict__ A, const __half* __restrict__ B,
    const float* __restrict__ bias, void* __restrict__ Cv,
    int M, int N, int K, size_t strA, size_t strB, size_t strC)
{
    extern __shared__ float smem[];
    const int tid  = threadIdx.x;
    const int lane = tid & 31, warp = tid >> 5;
    const int wm = warp >> 2, wn = warp & 3;
    const int row0 = blockIdx.y * 128, col0 = blockIdx.x * 128;

    A += (size_t)blockIdx.z * strA;
    B += (size_t)blockIdx.z * strB;

    const uint32_t sA = smem_u32(smem);
    const uint32_t sB = sA + SSTAGES * SSM_SZ;
    const int ktiles = K / KCHUNK;

    fill_stage_s(A, B, M, K, row0, col0, 0, sA, sB, tid);
    fill_stage_s(A, B, M, K, row0, col0, 1, sA + SSM_SZ, sB + SSM_SZ, tid);

    float acc[4][4][4];
#pragma unroll
    for (int i = 0; i < 4; i++)
#pragma unroll
        for (int j = 0; j < 4; j++)
#pragma unroll
            for (int k = 0; k < 4; k++) acc[i][j][k] = 0.0f;

    const int aRow = wm * 64 + ((lane >> 3) & 1) * 8 + (lane & 7);
    const int bRow = wn * 32 + ((lane >> 3) & 1) * 8 + (lane & 7);
    const uint32_t colSel = ((lane >> 4) & 1) * 16;
    const uint32_t xorv = ((uint32_t)lane & 7u) << 4;

    for (int it = 0; it < ktiles; it++) {
        if (it < ktiles - 1) asm volatile("cp.async.wait_group 1;" ::: "memory");
        else                 asm volatile("cp.async.wait_group 0;" ::: "memory");
        __syncthreads();
        const int st = it % 3;
        const uint32_t bA = sA + st * SSM_SZ;
        const uint32_t bB = sB + st * SSM_SZ;
        if (it + 2 < ktiles) {
            const int r = it + 2;
            fill_stage_s(A, B, M, K, row0, col0, r,
                         sA + (r % 3) * SSM_SZ, sB + (r % 3) * SSM_SZ, tid);
        }
#pragma unroll
        for (int ks = 0; ks < 4; ks++) {
            uint32_t a[4][4], bb[2][4];
            const uint32_t cb = ((uint32_t)(ks * 32) + colSel) ^ xorv;
#pragma unroll
            for (int mf = 0; mf < 4; mf++) {
                uint32_t ad = bA + (uint32_t)(aRow + mf * 16) * 128 + cb;
                LDSM4(a[mf][0], a[mf][1], a[mf][2], a[mf][3], ad);
            }
#pragma unroll
            for (int ng = 0; ng < 2; ng++) {
                uint32_t bd = bB + (uint32_t)(bRow + ng * 16) * 128 + cb;
                LDSM4(bb[ng][0], bb[ng][1], bb[ng][2], bb[ng][3], bd);
            }
#pragma unroll
            for (int mf = 0; mf < 4; mf++)
#pragma unroll
                for (int nf = 0; nf < 4; nf++) {
                    const int ng = nf >> 1, lo = nf & 1;
                    MMA_F16(acc[mf][nf], a[mf], bb[ng][lo], bb[ng][2 + lo]);
                }
        }
    }

#pragma unroll
    for (int mf = 0; mf < 4; mf++) {
        const int r0 = row0 + wm * 64 + mf * 16 + (lane >> 2);
        const int r8 = r0 + 8;
        float pos0 = 0.f, pos8 = 0.f;
        if (KV_EPI) {
            pos0 = ((r0 & 31) < 16) ? 2.0f : 22.0f;
            pos8 = ((r8 & 31) < 16) ? 2.0f : 22.0f;
        }
#pragma unroll
        for (int nf = 0; nf < 4; nf++) {
            const int c = col0 + wn * 32 + nf * 8 + (lane & 3) * 2;
            const float2 bv = *(const float2*)(bias + c);
            float o0 = acc[mf][nf][0] + bv.x;
            float o1 = acc[mf][nf][1] + bv.y;
            float o2 = acc[mf][nf][2] + bv.x;
            float o3 = acc[mf][nf][3] + bv.y;
            if (KV_EPI && c < DIM) {
                const int i = (c & 127) >> 1;
                const float fr = exp2f(-(float)i * (LOG2_10000 / 64.0f));
                float sn, cs;
                sincosf(pos0 * fr, &sn, &cs);
                float t0 = o0 * cs - o1 * sn;
                o1 = o1 * cs + o0 * sn; o0 = t0;
                sincosf(pos8 * fr, &sn, &cs);
                float t2 = o2 * cs - o3 * sn;
                o3 = o3 * cs + o2 * sn; o2 = t2;
            }
            if (KV_EPI) {
                if (c < DIM) {   // k half -> fp16
                    if (r0 < M) *(__half2*)(g_kh + (size_t)r0 * DIM + c) = __floats2half2_rn(o0, o1);
                    if (r8 < M) *(__half2*)(g_kh + (size_t)r8 * DIM + c) = __floats2half2_rn(o2, o3);
                } else {         // v half -> fp16
                    if (r0 < M) *(__half2*)(g_vh + (size_t)r0 * DIM + c - DIM) = __floats2half2_rn(o0, o1);
                    if (r8 < M) *(__half2*)(g_vh + (size_t)r8 * DIM + c - DIM) = __floats2half2_rn(o2, o3);
                }
            } else if (HALF_OUT) {
                __half* C = (__half*)Cv + (size_t)blockIdx.z * strC;
                if (r0 < M) *(__half2*)(C + (size_t)r0 * N + c) = __floats2half2_rn(o0, o1);
                if (r8 < M) *(__half2*)(C + (size_t)r8 * N + c) = __floats2half2_rn(o2, o3);
            } else {
                float* C = (float*)Cv + (size_t)blockIdx.z * strC;
                if (r0 < M) *(float2*)(C + (size_t)r0 * N + c) = make_float2(o0, o1);
                if (r8 < M) *(float2*)(C + (size_t)r8 * N + c) = make_float2(o2, o3);
            }
        }
    }
}

// ======== q GEMM with fused RoPE + scores + softmax -> probs ========
// grid (head=12, token-tile=256). After mainloop, stage smem is reused:
//   qtile fp16 [128 x 128]  at offset 0      (2 kchunks x 16KB)
//   kA tile fp16 [32 x 128] at offset 32768  (2 kchunks x 4KB)
//   kB tile fp16 [32 x 128] at offset 40960
__global__ void __launch_bounds__(256, 2) gemm_q_scores(
    const __half* __restrict__ A, const __half* __restrict__ B,
    const float* __restrict__ bias)
{
    extern __shared__ float smem[];
    char* sbytes = (char*)smem;
    const int tid  = threadIdx.x;
    const int lane = tid & 31, warp = tid >> 5;
    const int wm = warp >> 2, wn = warp & 3;
    const int row0 = blockIdx.y * 128;          // global token base
    const int head = blockIdx.x;
    const int col0 = head * 128;

    const uint32_t sA = smem_u32(smem);
    const uint32_t sB = sA + SSTAGES * SSM_SZ;
    const int ktiles = DIM / KCHUNK;            // 24

    fill_stage_s(A, B, N_TOK, DIM, row0, col0, 0, sA, sB, tid);
    fill_stage_s(A, B, N_TOK, DIM, row0, col0, 1, sA + SSM_SZ, sB + SSM_SZ, tid);

    float acc[4][4][4];
#pragma unroll
    for (int i = 0; i < 4; i++)
#pragma unroll
        for (int j = 0; j < 4; j++)
#pragma unroll
            for (int k = 0; k < 4; k++) acc[i][j][k] = 0.0f;

    const int aRow = wm * 64 + ((lane >> 3) & 1) * 8 + (lane & 7);
    const int bRow = wn * 32 + ((lane >> 3) & 1) * 8 + (lane & 7);
    const uint32_t colSel = ((lane >> 4) & 1) * 16;
    const uint32_t xorv = ((uint32_t)lane & 7u) << 4;

    for (int it = 0; it < ktiles; it++) {
        if (it < ktiles - 1) asm volatile("cp.async.wait_group 1;" ::: "memory");
        else                 asm volatile("cp.async.wait_group 0;" ::: "memory");
        __syncthreads();
        const int st = it % 3;
        const uint32_t bA = sA + st * SSM_SZ;
        const uint32_t bB = sB + st * SSM_SZ;
        if (it + 2 < ktiles) {
            const int r = it + 2;
            fill_stage_s(A, B, N_TOK, DIM, row0, col0, r,
                         sA + (r % 3) * SSM_SZ, sB + (r % 3) * SSM_SZ, tid);
        }
#pragma unroll
        for (int ks = 0; ks < 4; ks++) {
            uint32_t a[4][4], bb[2][4];
            const uint32_t cb = ((uint32_t)(ks * 32) + colSel) ^ xorv;
#pragma unroll
            for (int mf = 0; mf < 4; mf++) {
                uint32_t ad = bA + (uint32_t)(aRow + mf * 16) * 128 + cb;
                LDSM4(a[mf][0], a[mf][1], a[mf][2], a[mf][3], ad);
            }
#pragma unroll
            for (int ng = 0; ng < 2; ng++) {
                uint32_t bd = bB + (uint32_t)(bRow + ng * 16) * 128 + cb;
                LDSM4(bb[ng][0], bb[ng][1], bb[ng][2], bb[ng][3], bd);
            }
#pragma unroll
            for (int mf = 0; mf < 4; mf++)
#pragma unroll
                for (int nf = 0; nf < 4; nf++) {
                    const int ng = nf >> 1, lo = nf & 1;
                    MMA_F16(acc[mf][nf], a[mf], bb[ng][lo], bb[ng][2 + lo]);
                }
        }
    }
    __syncthreads();   // all stage consumers done; smem now reusable

    // ---- issue k-tile loads (frames fA, fB) into reused smem ----
    const int fA = row0 / S_SP;
    const int lastTok = (row0 + 127 < N_TOK) ? row0 + 127 : N_TOK - 1;
    const int fB = lastTok / S_SP;
    {
        const int fsel[2] = {fA, fB};
#pragma unroll
        for (int g = 0; g < 4; g++) {
            int i = tid + g * 256;
            int tl = i >> 9, kt = (i >> 8) & 1, row = (i >> 3) & 31, ch = i & 7;
            const __half* src = g_kh + (size_t)(fsel[tl] * 32 + row) * DIM + col0 + kt * 64 + ch * 8;
            uint32_t dst = sA + 32768u + (uint32_t)tl * 8192u + (uint32_t)kt * 4096u +
                           (uint32_t)row * 128u + (((uint32_t)ch * 16u) ^ (((uint32_t)row & 7u) << 4));
            asm volatile("cp.async.cg.shared.global [%0], [%1], 16;" :: "r"(dst), "l"(src));
        }
        asm volatile("cp.async.commit_group;");
    }

    // ---- RoPE epilogue -> qtile smem (fp16, K-major, 2 kchunks, swizzled) ----
#pragma unroll
    for (int mf = 0; mf < 4; mf++) {
        const int rr0 = wm * 64 + mf * 16 + (lane >> 2);     // local rows
        const int rr8 = rr0 + 8;
        const int t0 = row0 + rr0, t8 = row0 + rr8;
        const float pos0 = g_pos[(t0 < N_TOK) ? t0 : (N_TOK - 1)];
        const float pos8 = g_pos[(t8 < N_TOK) ? t8 : (N_TOK - 1)];
#pragma unroll
        for (int nf = 0; nf < 4; nf++) {
            const int crel = wn * 32 + nf * 8 + (lane & 3) * 2;   // head-local col
            const float2 bv = *(const float2*)(bias + col0 + crel);
            float o0 = acc[mf][nf][0] + bv.x;
            float o1 = acc[mf][nf][1] + bv.y;
            float o2 = acc[mf][nf][2] + bv.x;
            float o3 = acc[mf][nf][3] + bv.y;
            const int i = crel >> 1;
            const float fr = exp2f(-(float)i * (LOG2_10000 / 64.0f));
            float sn, cs;
            sincosf(pos0 * fr, &sn, &cs);
            float tt = o0 * cs - o1 * sn;
            o1 = o1 * cs + o0 * sn; o0 = tt;
            sincosf(pos8 * fr, &sn, &cs);
            tt = o2 * cs - o3 * sn;
            o3 = o3 * cs + o2 * sn; o2 = tt;
            // store to qtile smem
            const int kt = crel >> 6, hc = crel & 63;
            uint32_t off0 = (uint32_t)kt * 16384u + (uint32_t)rr0 * 128u +
                            (((uint32_t)hc * 2u) ^ (((uint32_t)rr0 & 7u) << 4));
            uint32_t off8 = (uint32_t)kt * 16384u + (uint32_t)rr8 * 128u +
                            (((uint32_t)hc * 2u) ^ (((uint32_t)rr8 & 7u) << 4));
            *(__half2*)(sbytes + off0) = __floats2half2_rn(o0, o1);
            *(__half2*)(sbytes + off8) = __floats2half2_rn(o2, o3);
        }
    }
    asm volatile("cp.async.wait_group 0;" ::: "memory");
    __syncthreads();

    // ---- score MMA: warp w -> tokens w*16..w*16+15, 64 keys (fA set | fB set) ----
    float sacc[8][4];
#pragma unroll
    for (int i = 0; i < 8; i++)
#pragma unroll
        for (int j = 0; j < 4; j++) sacc[i][j] = 0.0f;

    const int aRow2 = warp * 16 + ((lane >> 3) & 1) * 8 + (lane & 7);
    const int bRow2 = ((lane >> 3) & 1) * 8 + (lane & 7);
#pragma unroll
    for (int kf = 0; kf < 8; kf++) {
        const uint32_t cb = ((uint32_t)((kf & 3) * 32) + colSel) ^ xorv;
        uint32_t a0, a1, a2, a3;
        LDSM4(a0, a1, a2, a3, sA + (uint32_t)(kf >> 2) * 16384u + (uint32_t)aRow2 * 128u + cb);
        uint32_t afrag[4] = {a0, a1, a2, a3};
#pragma unroll
        for (int tl = 0; tl < 2; tl++) {
#pragma unroll
            for (int ng = 0; ng < 2; ng++) {
                uint32_t b0, b1, b2, b3;
                uint32_t bd = sA + 32768u + (uint32_t)tl * 8192u + (uint32_t)(kf >> 2) * 4096u +
                              (uint32_t)(ng * 16 + bRow2) * 128u + cb;
                LDSM4(b0, b1, b2, b3, bd);
                MMA_F16(sacc[tl * 4 + ng * 2 + 0], afrag, b0, b2);
                MMA_F16(sacc[tl * 4 + ng * 2 + 1], afrag, b1, b3);
            }
        }
    }

    // ---- softmax over the row's 32 keys + store probs ----
    {
        const int rA = lane >> 2;
        const int tok0 = row0 + warp * 16 + rA;
        const int tok8 = tok0 + 8;
        const int base0 = (tok0 / S_SP == fA) ? 0 : 4;   // which 32-key set
        const int base8 = (tok8 / S_SP == fA) ? 0 : 4;
        const float scl = 0.08838834764831845f;

        float e0[8], e8[8];
        float mx0 = -1e30f, mx8 = -1e30f;
#pragma unroll
        for (int nf = 0; nf < 4; nf++) {
            mx0 = fmaxf(mx0, fmaxf(sacc[base0 + nf][0], sacc[base0 + nf][1]));
            mx8 = fmaxf(mx8, fmaxf(sacc[base8 + nf][2], sacc[base8 + nf][3]));
        }
        mx0 = fmaxf(mx0, __shfl_xor_sync(0xFFFFFFFFu, mx0, 1));
        mx8 = fmaxf(mx8, __shfl_xor_sync(0xFFFFFFFFu, mx8, 1));
        mx0 = fmaxf(mx0, __shfl_xor_sync(0xFFFFFFFFu, mx0, 2));
        mx8 = fmaxf(mx8, __shfl_xor_sync(0xFFFFFFFFu, mx8, 2));
        mx0 *= scl; mx8 *= scl;

        float s0 = 0.f, s8 = 0.f;
#pragma unroll
        for (int nf = 0; nf < 4; nf++) {
            e0[nf * 2 + 0] = __expf(sacc[base0 + nf][0] * scl - mx0);
            e0[nf * 2 + 1] = __expf(sacc[base0 + nf][1] * scl - mx0);
            e8[nf * 2 + 0] = __expf(sacc[base8 + nf][2] * scl - mx8);
            e8[nf * 2 + 1] = __expf(sacc[base8 + nf][3] * scl - mx8);
            s0 += e0[nf * 2] + e0[nf * 2 + 1];
            s8 += e8[nf * 2] + e8[nf * 2 + 1];
        }
        s0 += __shfl_xor_sync(0xFFFFFFFFu, s0, 1);
        s8 += __shfl_xor_sync(0xFFFFFFFFu, s8, 1);
        s0 += __shfl_xor_sync(0xFFFFFFFFu, s0, 2);
        s8 += __shfl_xor_sync(0xFFFFFFFFu, s8, 2);
        const float inv0 = 1.0f / s0, inv8 = 1.0f / s8;

#pragma unroll
        for (int nf = 0; nf < 4; nf++) {
            const int ck = nf * 8 + (lane & 3) * 2;
            if (tok0 < N_TOK)
                *(__half2*)(g_probsh + (size_t)tok0 * PKDIM + head * NA + ck) =
                    __floats2half2_rn(e0[nf * 2] * inv0, e0[nf * 2 + 1] * inv0);
            if (tok8 < N_TOK)
                *(__half2*)(g_probsh + (size_t)tok8 * PKDIM + head * NA + ck) =
                    __floats2half2_rn(e8[nf * 2] * inv8, e8[nf * 2 + 1] * inv8);
        }
    }
}

// ---------------- W2 fold on tensor cores ------------------------------------
__global__ void __launch_bounds__(128) w2_mma_kernel() {
    const int mt = blockIdx.x;
    const int h  = blockIdx.y;
    const int b  = blockIdx.z;
    __shared__ __align__(16) char smem[2 * 16384 + 2 * 4096];

    const int tid = threadIdx.x;
    const int lane = tid & 31, warp = tid >> 5;
    const uint32_t sA = smem_u32(smem);
    const uint32_t sB = sA + 2 * 16384;

#pragma unroll
    for (int g = 0; g < 16; g++) {
        int i = tid + g * 128;
        int kt = i >> 10, row = (i >> 3) & 127, ch = i & 7;
        uint32_t dst = sA + kt * 16384 + (uint32_t)row * 128u +
                       (((uint32_t)ch * 16u) ^ (((uint32_t)row & 7u) << 4));
        const __half* src = g_pwh + (size_t)(mt * 128 + row) * DIM + h * HD + kt * KCHUNK + ch * 8;
        asm volatile("cp.async.cg.shared.global [%0], [%1], 16;" :: "r"(dst), "l"(src));
    }
#pragma unroll
    for (int g = 0; g < 4; g++) {
        int i = tid + g * 128;
        int kt = i >> 8, row = (i >> 3) & 31, ch = i & 7;
        uint32_t dst = sB + kt * 4096 + (uint32_t)row * 128u +
                       (((uint32_t)ch * 16u) ^ (((uint32_t)row & 7u) << 4));
        const __half* src = g_vh + (size_t)(b * 32 + row) * DIM + h * HD + kt * KCHUNK + ch * 8;
        asm volatile("cp.async.cg.shared.global [%0], [%1], 16;" :: "r"(dst), "l"(src));
    }
    asm volatile("cp.async.commit_group;");
    asm volatile("cp.async.wait_group 0;" ::: "memory");
    __syncthreads();

    float acc[2][4][4];
#pragma unroll
    for (int i = 0; i < 2; i++)
#pragma unroll
        for (int j = 0; j < 4; j++)
#pragma unroll
            for (int k = 0; k < 4; k++) acc[i][j][k] = 0.0f;

    const int aRow = warp * 32 + ((lane >> 3) & 1) * 8 + (lane & 7);
    const int bRow = ((lane >> 3) & 1) * 8 + (lane & 7);
    const uint32_t colSel = ((lane >> 4) & 1) * 16;
    const uint32_t xorv = ((uint32_t)lane & 7u) << 4;

#pragma unroll
    for (int kt = 0; kt < 2; kt++) {
        const uint32_t bA = sA + kt * 16384;
        const uint32_t bB = sB + kt * 4096;
#pragma unroll
        for (int ks = 0; ks < 4; ks++) {
            uint32_t a[2][4], bb[2][4];
            const uint32_t cb = ((uint32_t)(ks * 32) + colSel) ^ xorv;
#pragma unroll
            for (int mf = 0; mf < 2; mf++) {
                uint32_t ad = bA + (uint32_t)(aRow + mf * 16) * 128 + cb;
                LDSM4(a[mf][0], a[mf][1], a[mf][2], a[mf][3], ad);
            }
#pragma unroll
            for (int ng = 0; ng < 2; ng++) {
                uint32_t bd = bB + (uint32_t)(bRow + ng * 16) * 128 + cb;
                LDSM4(bb[ng][0], bb[ng][1], bb[ng][2], bb[ng][3], bd);
            }
#pragma unroll
            for (int mf = 0; mf < 2; mf++)
#pragma unroll
                for (int nf = 0; nf < 4; nf++) {
                    const int ng = nf >> 1, lo = nf & 1;
                    MMA_F16(acc[mf][nf], a[mf], bb[ng][lo], bb[ng][2 + lo]);
                }
        }
    }

    __half* dst = g_w2h + (size_t)b * DIM * PKDIM + h * NA;
#pragma unroll
    for (int mf = 0; mf < 2; mf++) {
        const int r0 = mt * 128 + warp * 32 + mf * 16 + (lane >> 2);
        const int r8 = r0 + 8;
#pragma unroll
        for (int nf = 0; nf < 4; nf++) {
            const int c = nf * 8 + (lane & 3) * 2;
            *(__half2*)(dst + (size_t)r0 * PKDIM + c) = __floats2half2_rn(acc[mf][nf][0], acc[mf][nf][1]);
            *(__half2*)(dst + (size_t)r8 * PKDIM + c) = __floats2half2_rn(acc[mf][nf][2], acc[mf][nf][3]);
        }
    }
}

// ---------------- launch (single stream) ----------------
extern "C" void kernel_launch(void* const* d_in, const int* in_sizes, int n_in,
                              void* d_out, int out_size)
{
    const float* x    = (const float*)d_in[0];
    const float* ehs  = (const float*)d_in[1];
    const float* amap = (const float*)d_in[2];
    const float* q_w  = (const float*)d_in[3];
    const float* q_b  = (const float*)d_in[4];
    const float* kv_w = (const float*)d_in[5];
    const float* kv_b = (const float*)d_in[6];
    const float* p_w  = (const float*)d_in[7];
    const float* p_b  = (const float*)d_in[8];
    float* out = (float*)d_out;

    __half *xh, *qwh, *kvwh, *ehsh, *probsh, *w2h;
    cudaGetSymbolAddress((void**)&xh,     g_xh);
    cudaGetSymbolAddress((void**)&qwh,    g_qwh);
    cudaGetSymbolAddress((void**)&kvwh,   g_kvwh);
    cudaGetSymbolAddress((void**)&ehsh,   g_ehsh);
    cudaGetSymbolAddress((void**)&probsh, g_probsh);
    cudaGetSymbolAddress((void**)&w2h,    g_w2h);

    cudaFuncSetAttribute((const void*)gemm_q_scores,
                         cudaFuncAttributeMaxDynamicSharedMemorySize, SSM_TOT);
    cudaFuncSetAttribute((const void*)gemm_f16_small<false, false>,
                         cudaFuncAttributeMaxDynamicSharedMemorySize, SSM_TOT);
    cudaFuncSetAttribute((const void*)gemm_f16_small<false, true>,
                         cudaFuncAttributeMaxDynamicSharedMemorySize, SSM_TOT);

    // routing positions
    minmax_kernel<<<1, 512>>>(amap);
    pos_kernel<<<(N_TOK + 255) / 256, 256>>>(amap);

    // fp16 conversions
    cvt_half_kernel<<<CVT_GRID(N_TOK * DIM / 4), 256>>>(x, xh, N_TOK * DIM / 4);
    cvt_weights_kernel<<<(SEG3 + 1023) / 1024, 256>>>(q_w, p_w, ehs, kv_w);

    // kv projection with fused split + RoPE(k): k -> fp16 g_kh, v -> fp16 g_vh
    gemm_f16_small<false, true><<<dim3((2 * DIM) / 128, (KV_ROWS + 127) / 128, 1), 256, SSM_TOT>>>(
        ehsh, kvwh, kv_b, nullptr, KV_ROWS, 2 * DIM, ENC, 0, 0, 0);

    // q GEMM + fused RoPE + scores + softmax -> probs
    gemm_q_scores<<<dim3(NHEADS, (N_TOK + 127) / 128), 256, SSM_TOT>>>(xh, qwh, q_b);

    // W2 = V @ proj (tensor cores) -> fp16
    w2_mma_kernel<<<dim3(DIM / 128, NHEADS, N_T), 128>>>();

    // out[b] = probs[b] @ W2[b]^T + p_b   (batched, K=384)
    gemm_f16_small<false, false><<<dim3(DIM / 128, (S_SP + 127) / 128, N_T), 256, SSM_TOT>>>(
        probsh, w2h, p_b, out, S_SP, DIM, PKDIM,
        (size_t)S_SP * PKDIM, (size_t)DIM * PKDIM, (size_t)S_SP * DIM);
}